// round 1
// baseline (speedup 1.0000x reference)
#include <cuda_runtime.h>
#include <math.h>

#define B_    4
#define T_    4096
#define D_    1024
#define H_    16
#define R_    32
#define DH_   64
#define BH_   64
#define MROWS 16384
#define NCH   8

// ---------------- scratch (device globals; no allocation) ----------------
__device__ float g_normed[(size_t)MROWS * D_];       // 64 MB
__device__ float g_K[(size_t)BH_ * T_ * R_];         // 32 MB
__device__ float g_Q[(size_t)BH_ * T_ * R_];         // 32 MB
__device__ float g_V[(size_t)BH_ * T_ * DH_];        // 64 MB
__device__ float g_part[(size_t)BH_ * NCH * 4096];   // 8 MB
__device__ float g_Tmat[(size_t)BH_ * DH_ * R_];     // 0.5 MB
__device__ float g_full[(size_t)MROWS * D_];         // 64 MB

// ---------------- LayerNorm ----------------
__global__ __launch_bounds__(256)
void ln_kernel(const float* __restrict__ x, const float* __restrict__ sc,
               const float* __restrict__ bi)
{
    int row = blockIdx.x;
    int tid = threadIdx.x;
    const float4* xr = (const float4*)(x + (size_t)row * D_);
    float4 v = xr[tid];
    float s  = v.x + v.y + v.z + v.w;
    float ss = v.x*v.x + v.y*v.y + v.z*v.z + v.w*v.w;
    __shared__ float rs[8], rss[8];
    #pragma unroll
    for (int o = 16; o > 0; o >>= 1) {
        s  += __shfl_down_sync(0xffffffffu, s,  o);
        ss += __shfl_down_sync(0xffffffffu, ss, o);
    }
    int w = tid >> 5, l = tid & 31;
    if (l == 0) { rs[w] = s; rss[w] = ss; }
    __syncthreads();
    if (tid == 0) {
        float a = 0.f, b = 0.f;
        #pragma unroll
        for (int i = 0; i < 8; i++) { a += rs[i]; b += rss[i]; }
        rs[0] = a; rss[0] = b;
    }
    __syncthreads();
    float mu   = rs[0]  * (1.0f / D_);
    float var  = rss[0] * (1.0f / D_) - mu * mu;
    float rstd = rsqrtf(var + 1e-5f);
    float4 s4 = ((const float4*)sc)[tid];
    float4 b4 = ((const float4*)bi)[tid];
    float4 o;
    o.x = (v.x - mu) * rstd * s4.x + b4.x;
    o.y = (v.y - mu) * rstd * s4.y + b4.y;
    o.z = (v.z - mu) * rstd * s4.z + b4.z;
    o.w = (v.w - mu) * rstd * s4.w + b4.w;
    ((float4*)(g_normed + (size_t)row * D_))[tid] = o;
}

// ---------------- SGEMM 128x128x16, 8x8 per thread ----------------
// mode 0: C -> g_K (head layout, hd=32); 1: g_Q; 2: g_V (hd=64); 3: Cext plain * sigmoid(gate)
__global__ __launch_bounds__(256, 2)
void sgemm_kernel(const float* __restrict__ Bw, const float* __restrict__ gate,
                  float* __restrict__ Cext, int N, int mode)
{
    const float* A = (mode == 3) ? g_full : g_normed;
    __shared__ __align__(16) float As[16][128];
    __shared__ __align__(16) float Bs[16][128];
    int tid = threadIdx.x;
    int m0 = blockIdx.y * 128;
    int n0 = blockIdx.x * 128;
    int ty = tid >> 4, tx = tid & 15;

    float acc[8][8];
    #pragma unroll
    for (int i = 0; i < 8; i++)
        #pragma unroll
        for (int j = 0; j < 8; j++) acc[i][j] = 0.f;

    for (int k0 = 0; k0 < D_; k0 += 16) {
        #pragma unroll
        for (int i = 0; i < 2; i++) {
            int idx = tid * 2 + i;
            int ar = idx >> 2, ak = (idx & 3) * 4;
            float4 av = *(const float4*)&A[(size_t)(m0 + ar) * D_ + k0 + ak];
            As[ak + 0][ar] = av.x; As[ak + 1][ar] = av.y;
            As[ak + 2][ar] = av.z; As[ak + 3][ar] = av.w;
            int br = idx >> 5, bc = (idx & 31) * 4;
            *(float4*)&Bs[br][bc] = *(const float4*)&Bw[(size_t)(k0 + br) * N + n0 + bc];
        }
        __syncthreads();
        #pragma unroll
        for (int k = 0; k < 16; k++) {
            float a[8], b[8];
            *(float4*)&a[0] = *(const float4*)&As[k][ty * 4];
            *(float4*)&a[4] = *(const float4*)&As[k][ty * 4 + 64];
            *(float4*)&b[0] = *(const float4*)&Bs[k][tx * 4];
            *(float4*)&b[4] = *(const float4*)&Bs[k][tx * 4 + 64];
            #pragma unroll
            for (int i = 0; i < 8; i++)
                #pragma unroll
                for (int j = 0; j < 8; j++) acc[i][j] += a[i] * b[j];
        }
        __syncthreads();
    }

    if (mode == 3) {
        float g = 1.0f / (1.0f + expf(-gate[0]));
        #pragma unroll
        for (int qi = 0; qi < 2; qi++)
            #pragma unroll
            for (int ii = 0; ii < 4; ii++) {
                int m = m0 + qi * 64 + ty * 4 + ii;
                #pragma unroll
                for (int qj = 0; qj < 2; qj++)
                    #pragma unroll
                    for (int jj = 0; jj < 4; jj++) {
                        int n = n0 + qj * 64 + tx * 4 + jj;
                        Cext[(size_t)m * N + n] = g * acc[qi * 4 + ii][qj * 4 + jj];
                    }
            }
    } else {
        int hd = (mode == 2) ? 64 : 32;
        float* C = (mode == 0) ? g_K : (mode == 1) ? g_Q : g_V;
        #pragma unroll
        for (int qi = 0; qi < 2; qi++)
            #pragma unroll
            for (int ii = 0; ii < 4; ii++) {
                int m = m0 + qi * 64 + ty * 4 + ii;
                int b = m >> 12;          // /T_
                int t = m & (T_ - 1);
                #pragma unroll
                for (int qj = 0; qj < 2; qj++)
                    #pragma unroll
                    for (int jj = 0; jj < 4; jj++) {
                        int n = n0 + qj * 64 + tx * 4 + jj;
                        int h = n / hd;
                        int d = n - h * hd;
                        C[(((size_t)(b * H_ + h)) * T_ + t) * hd + d] =
                            acc[qi * 4 + ii][qj * 4 + jj];
                    }
            }
    }
}

// ---------------- partial G/M/Cv accumulation ----------------
__global__ __launch_bounds__(256)
void build_partial_kernel(const int* __restrict__ pl)
{
    int bh = blockIdx.x;
    int chunk = blockIdx.y;
    int P = *pl; if (P < 1) P = 1; if (P > T_ - 1) P = T_ - 1;
    int ch = (P + NCH - 1) / NCH;
    int lo = chunk * ch;
    int hi = min(lo + ch, P);

    const float* K = g_K + (size_t)bh * T_ * R_;
    const float* V = g_V + (size_t)bh * T_ * DH_;
    __shared__ __align__(16) float Ks[65][32];
    __shared__ __align__(16) float Vs[64][64];

    int tid = threadIdx.x;
    int r  = tid & 31, sg = tid >> 5;   // G/M: (r, sg*4..+3)
    int d  = tid & 63, rg = tid >> 6;   // Cv:  (d, rg*8..+7)
    float gacc[4] = {0, 0, 0, 0};
    float macc[4] = {0, 0, 0, 0};
    float cacc[8] = {0, 0, 0, 0, 0, 0, 0, 0};

    for (int t0 = lo; t0 < hi; t0 += 64) {
        int nrows = min(64, hi - t0);
        for (int idx = tid; idx < (nrows + 1) * 8; idx += 256) {
            int rr = idx >> 3, cq = (idx & 7) * 4;
            *(float4*)&Ks[rr][cq] = *(const float4*)&K[(size_t)(t0 + rr) * R_ + cq];
        }
        for (int idx = tid; idx < nrows * 16; idx += 256) {
            int rr = idx >> 4, cq = (idx & 15) * 4;
            *(float4*)&Vs[rr][cq] = *(const float4*)&V[(size_t)(t0 + rr) * DH_ + cq];
        }
        __syncthreads();
        for (int tt = 0; tt < nrows; tt++) {
            int t = t0 + tt;
            float kr  = Ks[tt][r];
            float ks0 = Ks[tt][sg * 4 + 0], ks1 = Ks[tt][sg * 4 + 1];
            float ks2 = Ks[tt][sg * 4 + 2], ks3 = Ks[tt][sg * 4 + 3];
            gacc[0] += kr * ks0; gacc[1] += kr * ks1;
            gacc[2] += kr * ks2; gacc[3] += kr * ks3;
            if (t < P - 1) {
                float kn = Ks[tt + 1][r];
                macc[0] += kn * ks0; macc[1] += kn * ks1;
                macc[2] += kn * ks2; macc[3] += kn * ks3;
            }
            float vv = Vs[tt][d];
            #pragma unroll
            for (int j = 0; j < 8; j++) cacc[j] += vv * Ks[tt][rg * 8 + j];
        }
        __syncthreads();
    }
    float* out = g_part + ((size_t)bh * NCH + chunk) * 4096;
    #pragma unroll
    for (int j = 0; j < 4; j++) {
        out[r * 32 + sg * 4 + j]        = gacc[j];
        out[1024 + r * 32 + sg * 4 + j] = macc[j];
    }
    #pragma unroll
    for (int j = 0; j < 8; j++) out[2048 + d * 32 + rg * 8 + j] = cacc[j];
}

// ---------------- per-head solve: Cholesky, Linv, Aw, sigma, Tmat ----------------
#define MM32(Cm, Am, Bm)                                                     \
    do {                                                                     \
        for (int e = tid; e < 1024; e += 256) {                              \
            int rr = e >> 5, cc = e & 31; float s = 0.f;                     \
            _Pragma("unroll") for (int k2 = 0; k2 < 32; k2++)                \
                s += Am[rr][k2] * Bm[k2][cc];                                \
            Cm[rr][cc] = s;                                                  \
        }                                                                    \
        __syncthreads();                                                     \
    } while (0)

__global__ __launch_bounds__(256)
void solve_kernel(const float* __restrict__ lridge, const float* __restrict__ lgamma)
{
    __shared__ float sG[32][33], sM[32][33], sL[32][33], sLi[32][33];
    __shared__ float sAw[32][33], sT[32][33];
    __shared__ float sCv[64][33], sBv[64][33];
    __shared__ float sScale;

    int bh = blockIdx.x;
    int tid = threadIdx.x;

    // reduce 8 partials
    const float* base = g_part + (size_t)bh * NCH * 4096;
    for (int idx = tid; idx < 4096; idx += 256) {
        float s = 0.f;
        #pragma unroll
        for (int c = 0; c < NCH; c++) s += base[(size_t)c * 4096 + idx];
        if (idx < 1024)      sG[idx >> 5][idx & 31] = s;
        else if (idx < 2048) sM[(idx - 1024) >> 5][idx & 31] = s;
        else { int e = idx - 2048; sCv[e >> 5][e & 31] = s; }
    }
    __syncthreads();
    if (tid < 32) sG[tid][tid] += expf(lridge[0]);
    __syncthreads();

    // Cholesky (warp 0), zero upper triangle of L
    if (tid < 32) {
        int i = tid;
        for (int j = 0; j < 32; j++) {
            if (i == j) {
                float s = sG[j][j];
                for (int k = 0; k < j; k++) s -= sL[j][k] * sL[j][k];
                sL[j][j] = sqrtf(fmaxf(s, 1e-30f));
            }
            __syncwarp();
            if (i > j) {
                float s = sG[i][j];
                for (int k = 0; k < j; k++) s -= sL[i][k] * sL[j][k];
                sL[i][j] = s / sL[j][j];
            } else if (i < j) {
                sL[i][j] = 0.f;
            }
            __syncwarp();
        }
        // Linv: forward solve L X = I, lane = column j
        int j = tid;
        for (int i2 = 0; i2 < 32; i2++) sLi[i2][j] = 0.f;
        for (int i2 = j; i2 < 32; i2++) {
            float s = (i2 == j) ? 1.f : 0.f;
            for (int k = j; k < i2; k++) s -= sL[i2][k] * sLi[k][j];
            sLi[i2][j] = s / sL[i2][i2];
        }
    }
    __syncthreads();

    // Aw = Li * M * Li^T
    MM32(sT, sLi, sM);                         // sT = Li @ M
    for (int e = tid; e < 1024; e += 256) {    // sAw = sT @ Li^T
        int rr = e >> 5, cc = e & 31; float s = 0.f;
        #pragma unroll
        for (int k2 = 0; k2 < 32; k2++) s += sT[rr][k2] * sLi[cc][k2];
        sAw[rr][cc] = s;
    }
    __syncthreads();

    // power iteration on Aw^T Aw for spectral norm (warp 0)
    if (tid < 32) {
        int i = tid;
        float v = 1.0f + 0.37f * (float)i;
        float sig = 0.f;
        for (int it = 0; it < 200; it++) {
            float u = 0.f;
            #pragma unroll
            for (int k = 0; k < 32; k++) u += sAw[i][k] * __shfl_sync(0xffffffffu, v, k);
            float w = 0.f;
            #pragma unroll
            for (int k = 0; k < 32; k++) w += sAw[k][i] * __shfl_sync(0xffffffffu, u, k);
            float n2 = w * w;
            #pragma unroll
            for (int o = 16; o > 0; o >>= 1) n2 += __shfl_xor_sync(0xffffffffu, n2, o);
            float nrm = sqrtf(n2);
            v = w / fmaxf(nrm, 1e-30f);
            sig = sqrtf(nrm);
        }
        if (i == 0) {
            float gamma = expf(lgamma[0]);
            float gc = fminf(gamma, 1.0f);
            float s0 = fmaxf(sig, 1e-8f);
            sScale = gc / fmaxf(s0, 1.0f);
        }
    }
    __syncthreads();
    float scl = sScale;
    for (int e = tid; e < 1024; e += 256) sAw[e >> 5][e & 31] *= scl;
    __syncthreads();

    // A4 = (Aw^2)^2 ; X = A4 @ Li ; X2 = L @ X
    MM32(sT, sAw, sAw);    // A2
    MM32(sM, sT, sT);      // A4 (overwrite M)
    MM32(sG, sM, sLi);     // X  (overwrite G)
    MM32(sT, sL, sG);      // X2

    // Bv = Cv @ Li^T @ Li
    for (int e = tid; e < 2048; e += 256) {
        int dd = e >> 5, rr = e & 31; float s = 0.f;
        #pragma unroll
        for (int k2 = 0; k2 < 32; k2++) s += sCv[dd][k2] * sLi[rr][k2];
        sBv[dd][rr] = s;
    }
    __syncthreads();
    for (int e = tid; e < 2048; e += 256) {
        int dd = e >> 5, rr = e & 31; float s = 0.f;
        #pragma unroll
        for (int k2 = 0; k2 < 32; k2++) s += sBv[dd][k2] * sLi[k2][rr];
        sCv[dd][rr] = s;     // Bv final
    }
    __syncthreads();

    // Tmat = Bv @ X2
    float* tm = g_Tmat + (size_t)bh * DH_ * R_;
    for (int e = tid; e < 2048; e += 256) {
        int dd = e >> 5, rr = e & 31; float s = 0.f;
        #pragma unroll
        for (int k2 = 0; k2 < 32; k2++) s += sCv[dd][k2] * sT[k2][rr];
        tm[dd * R_ + rr] = s;
    }
}

// ---------------- filter: full[b,t,h*64+d] = Tmat @ (k or q) ----------------
__global__ __launch_bounds__(256)
void filter_kernel(const int* __restrict__ pl)
{
    int bh = blockIdx.x;
    int t0 = blockIdx.y * 64;
    int P = *pl; if (P < 1) P = 1; if (P > T_ - 1) P = T_ - 1;

    __shared__ float Tm[DH_][R_ + 1];
    __shared__ float Qs[64][R_];
    int tid = threadIdx.x;

    for (int idx = tid; idx < DH_ * R_; idx += 256)
        Tm[idx >> 5][idx & 31] = g_Tmat[(size_t)bh * DH_ * R_ + idx];
    for (int idx = tid; idx < 64 * R_; idx += 256) {
        int tt = idx >> 5, rr = idx & 31;
        int t = t0 + tt;
        const float* src = (t < P) ? g_K : g_Q;
        Qs[tt][rr] = src[((size_t)bh * T_ + t) * R_ + rr];
    }
    __syncthreads();

    int d  = tid & 63;
    int tg = tid >> 6;
    float tm[R_];
    #pragma unroll
    for (int r = 0; r < R_; r++) tm[r] = Tm[d][r];
    int b = bh >> 4, h = bh & 15;
    #pragma unroll
    for (int k = 0; k < 16; k++) {
        int tt = tg * 16 + k;
        float s = 0.f;
        #pragma unroll
        for (int r = 0; r < R_; r++) s += tm[r] * Qs[tt][r];
        g_full[((size_t)(b * T_ + t0 + tt)) * D_ + h * DH_ + d] = s;
    }
}

// ---------------- launcher ----------------
extern "C" void kernel_launch(void* const* d_in, const int* in_sizes, int n_in,
                              void* d_out, int out_size)
{
    const float* hs     = (const float*)d_in[0];
    const float* Wk     = (const float*)d_in[1];
    const float* Wq     = (const float*)d_in[2];
    const float* Wv     = (const float*)d_in[3];
    const float* Wo     = (const float*)d_in[4];
    const float* lns    = (const float*)d_in[5];
    const float* lnb    = (const float*)d_in[6];
    const float* gate   = (const float*)d_in[7];
    const float* lridge = (const float*)d_in[8];
    const float* lgamma = (const float*)d_in[9];
    const int*   pl     = (const int*)d_in[10];
    float* out = (float*)d_out;

    ln_kernel<<<MROWS, 256>>>(hs, lns, lnb);

    dim3 gKQ(512 / 128, MROWS / 128);
    dim3 gV(1024 / 128, MROWS / 128);
    sgemm_kernel<<<gKQ, 256>>>(Wk, nullptr, nullptr, 512, 0);
    sgemm_kernel<<<gKQ, 256>>>(Wq, nullptr, nullptr, 512, 1);
    sgemm_kernel<<<gV, 256>>>(Wv, nullptr, nullptr, 1024, 2);

    dim3 gp(BH_, NCH);
    build_partial_kernel<<<gp, 256>>>(pl);
    solve_kernel<<<BH_, 256>>>(lridge, lgamma);

    dim3 gf(BH_, T_ / 64);
    filter_kernel<<<gf, 256>>>(pl);

    sgemm_kernel<<<gV, 256>>>(Wo, gate, out, 1024, 3);
}

// round 4
// speedup vs baseline: 3.8575x; 3.8575x over previous
#include <cuda_runtime.h>
#include <cuda_bf16.h>
#include <math.h>
#include <stdint.h>

#define B_    4
#define T_    4096
#define D_    1024
#define H_    16
#define R_    32
#define DH_   64
#define BH_   64
#define MROWS 16384
#define NCH   8

// ---- mma.sync GEMM tiling ----
#define BM 128
#define BN 128
#define BK 32
#define NCHUNK 32               // D_/BK
#define ST_A_H 0
#define ST_A_L (8*1024)
#define ST_B_H (16*1024)
#define ST_B_L (24*1024)
#define STAGE  (32*1024)
#define GEMM_SMEM (2*STAGE)

// ---------------- scratch (device globals; no allocation) ----------------
__device__ __align__(128) __nv_bfloat16 g_Ah[(size_t)MROWS * D_];
__device__ __align__(128) __nv_bfloat16 g_Al[(size_t)MROWS * D_];
__device__ __align__(128) __nv_bfloat16 g_Fh[(size_t)MROWS * D_];
__device__ __align__(128) __nv_bfloat16 g_Fl[(size_t)MROWS * D_];
__device__ __align__(128) __nv_bfloat16 g_Wth[(size_t)2048 * D_];   // [n][k] KQV
__device__ __align__(128) __nv_bfloat16 g_Wtl[(size_t)2048 * D_];
__device__ __align__(128) __nv_bfloat16 g_Woth[(size_t)1024 * D_];  // [n][k] Wo
__device__ __align__(128) __nv_bfloat16 g_Wotl[(size_t)1024 * D_];
__device__ float g_K[(size_t)BH_ * T_ * R_];
__device__ float g_Q[(size_t)BH_ * T_ * R_];
__device__ float g_V[(size_t)BH_ * T_ * DH_];
__device__ float g_part[(size_t)BH_ * NCH * 4096];
__device__ float g_Tmat[(size_t)BH_ * DH_ * R_];

// ---------------- PTX helpers (baseline ISA only) ----------------
__device__ __forceinline__ uint32_t smem_u32(const void* p) {
    uint32_t a;
    asm("{ .reg .u64 t; cvta.to.shared.u64 t, %1; cvt.u32.u64 %0, t; }" : "=r"(a) : "l"(p));
    return a;
}
__device__ __forceinline__ void cp16(uint32_t dst, const void* src) {
    asm volatile("cp.async.cg.shared.global [%0], [%1], 16;" :: "r"(dst), "l"(src) : "memory");
}
__device__ __forceinline__ void cp_commit() {
    asm volatile("cp.async.commit_group;" ::: "memory");
}
template<int N> __device__ __forceinline__ void cp_wait() {
    asm volatile("cp.async.wait_group %0;" :: "n"(N) : "memory");
}
__device__ __forceinline__ void ldsm4(uint32_t* r, uint32_t addr) {
    asm volatile("ldmatrix.sync.aligned.m8n8.x4.shared.b16 {%0,%1,%2,%3}, [%4];"
                 : "=r"(r[0]), "=r"(r[1]), "=r"(r[2]), "=r"(r[3]) : "r"(addr));
}
__device__ __forceinline__ void mma16816(float* c, const uint32_t* a, const uint32_t* b) {
    asm volatile("mma.sync.aligned.m16n8k16.row.col.f32.bf16.bf16.f32 "
                 "{%0,%1,%2,%3}, {%4,%5,%6,%7}, {%8,%9}, {%0,%1,%2,%3};"
                 : "+f"(c[0]), "+f"(c[1]), "+f"(c[2]), "+f"(c[3])
                 : "r"(a[0]), "r"(a[1]), "r"(a[2]), "r"(a[3]), "r"(b[0]), "r"(b[1]));
}
// 64B-row swizzle: XOR 16B-unit (bits 4,5) with row bits 1,2 (addr bits 7,8)
__device__ __forceinline__ uint32_t swz64(uint32_t b) { return b ^ ((b >> 3) & 0x30); }

// ---------------- LayerNorm -> bf16 hi/lo ----------------
__global__ __launch_bounds__(256)
void ln_split_kernel(const float* __restrict__ x, const float* __restrict__ sc,
                     const float* __restrict__ bi)
{
    int row = blockIdx.x;
    int tid = threadIdx.x;
    const float4* xr = (const float4*)(x + (size_t)row * D_);
    float4 v = xr[tid];
    float s  = v.x + v.y + v.z + v.w;
    float ss = v.x*v.x + v.y*v.y + v.z*v.z + v.w*v.w;
    __shared__ float rs[8], rss[8];
    #pragma unroll
    for (int o = 16; o > 0; o >>= 1) {
        s  += __shfl_down_sync(0xffffffffu, s,  o);
        ss += __shfl_down_sync(0xffffffffu, ss, o);
    }
    int w = tid >> 5, l = tid & 31;
    if (l == 0) { rs[w] = s; rss[w] = ss; }
    __syncthreads();
    if (tid == 0) {
        float a = 0.f, b = 0.f;
        #pragma unroll
        for (int i = 0; i < 8; i++) { a += rs[i]; b += rss[i]; }
        rs[0] = a; rss[0] = b;
    }
    __syncthreads();
    float mu   = rs[0]  * (1.0f / D_);
    float var  = rss[0] * (1.0f / D_) - mu * mu;
    float rstd = rsqrtf(var + 1e-5f);
    float4 s4 = ((const float4*)sc)[tid];
    float4 b4 = ((const float4*)bi)[tid];
    float o0 = (v.x - mu) * rstd * s4.x + b4.x;
    float o1 = (v.y - mu) * rstd * s4.y + b4.y;
    float o2 = (v.z - mu) * rstd * s4.z + b4.z;
    float o3 = (v.w - mu) * rstd * s4.w + b4.w;
    size_t base = (size_t)row * D_ + tid * 4;
    __nv_bfloat16 h0 = __float2bfloat16(o0), h1 = __float2bfloat16(o1);
    __nv_bfloat16 h2 = __float2bfloat16(o2), h3 = __float2bfloat16(o3);
    g_Ah[base+0] = h0; g_Ah[base+1] = h1; g_Ah[base+2] = h2; g_Ah[base+3] = h3;
    g_Al[base+0] = __float2bfloat16(o0 - __bfloat162float(h0));
    g_Al[base+1] = __float2bfloat16(o1 - __bfloat162float(h1));
    g_Al[base+2] = __float2bfloat16(o2 - __bfloat162float(h2));
    g_Al[base+3] = __float2bfloat16(o3 - __bfloat162float(h3));
}

// ---------------- weight transpose + split: W[K][N] -> dst[n][k] ----------------
__global__ __launch_bounds__(256)
void trans_split_kernel(const float* __restrict__ W, int N, int sel, int dstoff)
{
    __shared__ float tile[32][33];
    __nv_bfloat16* dh = (sel == 0 ? g_Wth : g_Woth) + (size_t)dstoff;
    __nv_bfloat16* dl = (sel == 0 ? g_Wtl : g_Wotl) + (size_t)dstoff;
    int n0 = blockIdx.x * 32, k0 = blockIdx.y * 32;
    int lane = threadIdx.x & 31, wrp = threadIdx.x >> 5;
    for (int i = wrp; i < 32; i += 8)
        tile[i][lane] = W[(size_t)(k0 + i) * N + n0 + lane];
    __syncthreads();
    for (int i = wrp; i < 32; i += 8) {
        float v = tile[lane][i];
        __nv_bfloat16 h = __float2bfloat16(v);
        dh[(size_t)(n0 + i) * D_ + k0 + lane] = h;
        dl[(size_t)(n0 + i) * D_ + k0 + lane] = __float2bfloat16(v - __bfloat162float(h));
    }
}

// ---------------- split-bf16 mma.sync GEMM ----------------
// mode 0: A=g_Ah/Al [16384][1024], B=g_Wth/Wtl [2048][1024], scatter K/Q/V
// mode 1: A=g_Fh/Fl,               B=g_Woth/Wotl,            out = sigmoid(gate)*C
__global__ __launch_bounds__(256, 1)
void mma_gemm_kernel(float* __restrict__ Cout, const float* __restrict__ gate, int mode)
{
    extern __shared__ __align__(1024) char sm[];
    uint32_t sbase = smem_u32(sm);

    const int tid  = threadIdx.x;
    const int lane = tid & 31;
    const int wid  = tid >> 5;
    const int wm   = wid & 3;        // m block (32 rows)
    const int wn   = wid >> 2;       // n block (64 cols)
    const int m0   = blockIdx.y * BM;
    const int ntb  = blockIdx.x * BN;

    const __nv_bfloat16* Agh = (mode == 0) ? g_Ah : g_Fh;
    const __nv_bfloat16* Agl = (mode == 0) ? g_Al : g_Fl;
    const __nv_bfloat16* Bgh = (mode == 0) ? g_Wth : g_Woth;
    const __nv_bfloat16* Bgl = (mode == 0) ? g_Wtl : g_Wotl;

    float acc[2][8][4];
    #pragma unroll
    for (int i = 0; i < 2; i++)
        #pragma unroll
        for (int j = 0; j < 8; j++)
            #pragma unroll
            for (int k = 0; k < 4; k++) acc[i][j][k] = 0.f;

    // ldmatrix per-lane address components
    const int a_r15 = lane & 15;                         // row within 16
    const int a_hi  = lane >> 4;                         // k-half
    const int b_nr  = (lane & 7) | ((lane >> 1) & 8);    // row within 16
    const int b_hi  = (lane >> 3) & 1;                   // k-half

    // loader: 512 16B-units per tensor, 2 per thread
    #define LOAD_STAGE(stg, koff)                                              \
        do {                                                                   \
            _Pragma("unroll")                                                  \
            for (int i_ = 0; i_ < 2; i_++) {                                   \
                int idx_ = tid + i_ * 256;                                     \
                int row_ = idx_ >> 2, u_ = idx_ & 3;                           \
                uint32_t d_ = swz64(row_ * 64 + u_ * 16);                      \
                size_t ka_ = (size_t)(m0 + row_) * D_ + (koff) + u_ * 8;       \
                size_t kb_ = (size_t)(ntb + row_) * D_ + (koff) + u_ * 8;      \
                cp16((stg) + ST_A_H + d_, Agh + ka_);                          \
                cp16((stg) + ST_A_L + d_, Agl + ka_);                          \
                cp16((stg) + ST_B_H + d_, Bgh + kb_);                          \
                cp16((stg) + ST_B_L + d_, Bgl + kb_);                          \
            }                                                                  \
            cp_commit();                                                       \
        } while (0)

    LOAD_STAGE(sbase, 0);

    for (int c = 0; c < NCHUNK; c++) {
        if (c + 1 < NCHUNK) {
            LOAD_STAGE(sbase + ((c + 1) & 1) * STAGE, (c + 1) * BK);
            cp_wait<1>();
        } else {
            cp_wait<0>();
        }
        __syncthreads();

        uint32_t st = sbase + (c & 1) * STAGE;
        #pragma unroll
        for (int ks = 0; ks < 2; ks++) {
            uint32_t ah0[4], ah1[4], al0[4], al1[4];
            {
                int u = ks * 2 + a_hi;
                uint32_t off0 = swz64((wm * 32 + a_r15) * 64 + u * 16);
                uint32_t off1 = swz64((wm * 32 + 16 + a_r15) * 64 + u * 16);
                ldsm4(ah0, st + ST_A_H + off0);
                ldsm4(ah1, st + ST_A_H + off1);
                ldsm4(al0, st + ST_A_L + off0);
                ldsm4(al1, st + ST_A_L + off1);
            }
            #pragma unroll
            for (int half = 0; half < 2; half++) {
                uint32_t bh[4][2], bl[4][2];
                #pragma unroll
                for (int p = 0; p < 2; p++) {
                    int u = ks * 2 + b_hi;
                    uint32_t off = swz64((wn * 64 + half * 32 + p * 16 + b_nr) * 64 + u * 16);
                    uint32_t r[4];
                    ldsm4(r, st + ST_B_H + off);
                    bh[p*2][0] = r[0]; bh[p*2][1] = r[1];
                    bh[p*2+1][0] = r[2]; bh[p*2+1][1] = r[3];
                    ldsm4(r, st + ST_B_L + off);
                    bl[p*2][0] = r[0]; bl[p*2][1] = r[1];
                    bl[p*2+1][0] = r[2]; bl[p*2+1][1] = r[3];
                }
                #pragma unroll
                for (int f = 0; f < 4; f++) {
                    int nf = half * 4 + f;
                    mma16816(acc[0][nf], ah0, bh[f]);
                    mma16816(acc[1][nf], ah1, bh[f]);
                    mma16816(acc[0][nf], ah0, bl[f]);
                    mma16816(acc[1][nf], ah1, bl[f]);
                    mma16816(acc[0][nf], al0, bh[f]);
                    mma16816(acc[1][nf], al1, bh[f]);
                }
            }
        }
        __syncthreads();
    }

    // ---- epilogue ----
    float gm = (mode == 1) ? (1.0f / (1.0f + expf(-gate[0]))) : 1.0f;
    #pragma unroll
    for (int mf = 0; mf < 2; mf++) {
        int mrow0 = m0 + wm * 32 + mf * 16 + (lane >> 2);
        #pragma unroll
        for (int nf = 0; nf < 8; nf++) {
            int n = ntb + wn * 64 + nf * 8 + (lane & 3) * 2;
            #pragma unroll
            for (int rh = 0; rh < 2; rh++) {
                int m = mrow0 + rh * 8;
                float2 v;
                v.x = gm * acc[mf][nf][rh * 2 + 0];
                v.y = gm * acc[mf][nf][rh * 2 + 1];
                if (mode == 1) {
                    *(float2*)(Cout + (size_t)m * 1024 + n) = v;
                } else {
                    int b = m >> 12, t = m & (T_ - 1);
                    float* dst;
                    if (n < 512) {
                        dst = g_K + (((size_t)(b * H_ + (n >> 5))) * T_ + t) * R_ + (n & 31);
                    } else if (n < 1024) {
                        int n2 = n - 512;
                        dst = g_Q + (((size_t)(b * H_ + (n2 >> 5))) * T_ + t) * R_ + (n2 & 31);
                    } else {
                        int nv = n - 1024;
                        dst = g_V + (((size_t)(b * H_ + (nv >> 6))) * T_ + t) * DH_ + (nv & 63);
                    }
                    *(float2*)dst = v;
                }
            }
        }
    }
}

// ---------------- partial G/M/Cv accumulation ----------------
__global__ __launch_bounds__(256)
void build_partial_kernel(const int* __restrict__ pl)
{
    int bh = blockIdx.x;
    int chunk = blockIdx.y;
    int P = *pl; if (P < 1) P = 1; if (P > T_ - 1) P = T_ - 1;
    int ch = (P + NCH - 1) / NCH;
    int lo = chunk * ch;
    int hi = min(lo + ch, P);

    const float* K = g_K + (size_t)bh * T_ * R_;
    const float* V = g_V + (size_t)bh * T_ * DH_;
    __shared__ __align__(16) float Ks[65][32];
    __shared__ __align__(16) float Vs[64][64];

    int tid = threadIdx.x;
    int r  = tid & 31, sg = tid >> 5;
    int d  = tid & 63, rg = tid >> 6;
    float gacc[4] = {0, 0, 0, 0};
    float macc[4] = {0, 0, 0, 0};
    float cacc[8] = {0, 0, 0, 0, 0, 0, 0, 0};

    for (int t0 = lo; t0 < hi; t0 += 64) {
        int nrows = min(64, hi - t0);
        for (int idx = tid; idx < (nrows + 1) * 8; idx += 256) {
            int rr = idx >> 3, cq = (idx & 7) * 4;
            *(float4*)&Ks[rr][cq] = *(const float4*)&K[(size_t)(t0 + rr) * R_ + cq];
        }
        for (int idx = tid; idx < nrows * 16; idx += 256) {
            int rr = idx >> 4, cq = (idx & 15) * 4;
            *(float4*)&Vs[rr][cq] = *(const float4*)&V[(size_t)(t0 + rr) * DH_ + cq];
        }
        __syncthreads();
        for (int tt = 0; tt < nrows; tt++) {
            int t = t0 + tt;
            float kr  = Ks[tt][r];
            float ks0 = Ks[tt][sg * 4 + 0], ks1 = Ks[tt][sg * 4 + 1];
            float ks2 = Ks[tt][sg * 4 + 2], ks3 = Ks[tt][sg * 4 + 3];
            gacc[0] += kr * ks0; gacc[1] += kr * ks1;
            gacc[2] += kr * ks2; gacc[3] += kr * ks3;
            if (t < P - 1) {
                float kn = Ks[tt + 1][r];
                macc[0] += kn * ks0; macc[1] += kn * ks1;
                macc[2] += kn * ks2; macc[3] += kn * ks3;
            }
            float vv = Vs[tt][d];
            #pragma unroll
            for (int j = 0; j < 8; j++) cacc[j] += vv * Ks[tt][rg * 8 + j];
        }
        __syncthreads();
    }
    float* out = g_part + ((size_t)bh * NCH + chunk) * 4096;
    #pragma unroll
    for (int j = 0; j < 4; j++) {
        out[r * 32 + sg * 4 + j]        = gacc[j];
        out[1024 + r * 32 + sg * 4 + j] = macc[j];
    }
    #pragma unroll
    for (int j = 0; j < 8; j++) out[2048 + d * 32 + rg * 8 + j] = cacc[j];
}

// ---------------- per-head solve ----------------
#define MM32(Cm, Am, Bm)                                                     \
    do {                                                                     \
        for (int e = tid; e < 1024; e += 256) {                              \
            int rr = e >> 5, cc = e & 31; float s = 0.f;                     \
            _Pragma("unroll") for (int k2 = 0; k2 < 32; k2++)                \
                s += Am[rr][k2] * Bm[k2][cc];                                \
            Cm[rr][cc] = s;                                                  \
        }                                                                    \
        __syncthreads();                                                     \
    } while (0)

__global__ __launch_bounds__(256)
void solve_kernel(const float* __restrict__ lridge, const float* __restrict__ lgamma)
{
    __shared__ float sG[32][33], sM[32][33], sL[32][33], sLi[32][33];
    __shared__ float sAw[32][33], sT[32][33];
    __shared__ float sCv[64][33], sBv[64][33];
    __shared__ float sScale;

    int bh = blockIdx.x;
    int tid = threadIdx.x;

    const float* base = g_part + (size_t)bh * NCH * 4096;
    for (int idx = tid; idx < 4096; idx += 256) {
        float s = 0.f;
        #pragma unroll
        for (int c = 0; c < NCH; c++) s += base[(size_t)c * 4096 + idx];
        if (idx < 1024)      sG[idx >> 5][idx & 31] = s;
        else if (idx < 2048) sM[(idx - 1024) >> 5][idx & 31] = s;
        else { int e = idx - 2048; sCv[e >> 5][e & 31] = s; }
    }
    __syncthreads();
    if (tid < 32) sG[tid][tid] += expf(lridge[0]);
    __syncthreads();

    if (tid < 32) {
        int i = tid;
        for (int j = 0; j < 32; j++) {
            if (i == j) {
                float s = sG[j][j];
                for (int k = 0; k < j; k++) s -= sL[j][k] * sL[j][k];
                sL[j][j] = sqrtf(fmaxf(s, 1e-30f));
            }
            __syncwarp();
            if (i > j) {
                float s = sG[i][j];
                for (int k = 0; k < j; k++) s -= sL[i][k] * sL[j][k];
                sL[i][j] = s / sL[j][j];
            } else if (i < j) {
                sL[i][j] = 0.f;
            }
            __syncwarp();
        }
        int j = tid;
        for (int i2 = 0; i2 < 32; i2++) sLi[i2][j] = 0.f;
        for (int i2 = j; i2 < 32; i2++) {
            float s = (i2 == j) ? 1.f : 0.f;
            for (int k = j; k < i2; k++) s -= sL[i2][k] * sLi[k][j];
            sLi[i2][j] = s / sL[i2][i2];
        }
    }
    __syncthreads();

    MM32(sT, sLi, sM);
    for (int e = tid; e < 1024; e += 256) {
        int rr = e >> 5, cc = e & 31; float s = 0.f;
        #pragma unroll
        for (int k2 = 0; k2 < 32; k2++) s += sT[rr][k2] * sLi[cc][k2];
        sAw[rr][cc] = s;
    }
    __syncthreads();

    if (tid < 32) {
        int i = tid;
        float v = 1.0f + 0.37f * (float)i;
        float sig = 0.f;
        for (int it = 0; it < 200; it++) {
            float u = 0.f;
            #pragma unroll
            for (int k = 0; k < 32; k++) u += sAw[i][k] * __shfl_sync(0xffffffffu, v, k);
            float w = 0.f;
            #pragma unroll
            for (int k = 0; k < 32; k++) w += sAw[k][i] * __shfl_sync(0xffffffffu, u, k);
            float n2 = w * w;
            #pragma unroll
            for (int o = 16; o > 0; o >>= 1) n2 += __shfl_xor_sync(0xffffffffu, n2, o);
            float nrm = sqrtf(n2);
            v = w / fmaxf(nrm, 1e-30f);
            sig = sqrtf(nrm);
        }
        if (i == 0) {
            float gamma = expf(lgamma[0]);
            float gc = fminf(gamma, 1.0f);
            float s0 = fmaxf(sig, 1e-8f);
            sScale = gc / fmaxf(s0, 1.0f);
        }
    }
    __syncthreads();
    float scl = sScale;
    for (int e = tid; e < 1024; e += 256) sAw[e >> 5][e & 31] *= scl;
    __syncthreads();

    MM32(sT, sAw, sAw);
    MM32(sM, sT, sT);
    MM32(sG, sM, sLi);
    MM32(sT, sL, sG);

    for (int e = tid; e < 2048; e += 256) {
        int dd = e >> 5, rr = e & 31; float s = 0.f;
        #pragma unroll
        for (int k2 = 0; k2 < 32; k2++) s += sCv[dd][k2] * sLi[rr][k2];
        sBv[dd][rr] = s;
    }
    __syncthreads();
    for (int e = tid; e < 2048; e += 256) {
        int dd = e >> 5, rr = e & 31; float s = 0.f;
        #pragma unroll
        for (int k2 = 0; k2 < 32; k2++) s += sBv[dd][k2] * sLi[k2][rr];
        sCv[dd][rr] = s;
    }
    __syncthreads();

    float* tm = g_Tmat + (size_t)bh * DH_ * R_;
    for (int e = tid; e < 2048; e += 256) {
        int dd = e >> 5, rr = e & 31; float s = 0.f;
        #pragma unroll
        for (int k2 = 0; k2 < 32; k2++) s += sCv[dd][k2] * sT[k2][rr];
        tm[dd * R_ + rr] = s;
    }
}

// ---------------- filter: F[b,t,h*64+d] = Tmat @ (k or q), split bf16 ----------------
__global__ __launch_bounds__(256)
void filter_kernel(const int* __restrict__ pl)
{
    int bh = blockIdx.x;
    int t0 = blockIdx.y * 64;
    int P = *pl; if (P < 1) P = 1; if (P > T_ - 1) P = T_ - 1;

    __shared__ float Tm[DH_][R_ + 1];
    __shared__ float Qs[64][R_];
    int tid = threadIdx.x;

    for (int idx = tid; idx < DH_ * R_; idx += 256)
        Tm[idx >> 5][idx & 31] = g_Tmat[(size_t)bh * DH_ * R_ + idx];
    for (int idx = tid; idx < 64 * R_; idx += 256) {
        int tt = idx >> 5, rr = idx & 31;
        int t = t0 + tt;
        const float* src = (t < P) ? g_K : g_Q;
        Qs[tt][rr] = src[((size_t)bh * T_ + t) * R_ + rr];
    }
    __syncthreads();

    int d  = tid & 63;
    int tg = tid >> 6;
    float tm[R_];
    #pragma unroll
    for (int r = 0; r < R_; r++) tm[r] = Tm[d][r];
    int b = bh >> 4, h = bh & 15;
    #pragma unroll
    for (int k = 0; k < 16; k++) {
        int tt = tg * 16 + k;
        float s = 0.f;
        #pragma unroll
        for (int r = 0; r < R_; r++) s += tm[r] * Qs[tt][r];
        size_t idx = ((size_t)(b * T_ + t0 + tt)) * D_ + h * DH_ + d;
        __nv_bfloat16 hv = __float2bfloat16(s);
        g_Fh[idx] = hv;
        g_Fl[idx] = __float2bfloat16(s - __bfloat162float(hv));
    }
}

// ---------------- launcher ----------------
extern "C" void kernel_launch(void* const* d_in, const int* in_sizes, int n_in,
                              void* d_out, int out_size)
{
    const float* hs     = (const float*)d_in[0];
    const float* Wk     = (const float*)d_in[1];
    const float* Wq     = (const float*)d_in[2];
    const float* Wv     = (const float*)d_in[3];
    const float* Wo     = (const float*)d_in[4];
    const float* lns    = (const float*)d_in[5];
    const float* lnb    = (const float*)d_in[6];
    const float* gate   = (const float*)d_in[7];
    const float* lridge = (const float*)d_in[8];
    const float* lgamma = (const float*)d_in[9];
    const int*   pl     = (const int*)d_in[10];
    float* out = (float*)d_out;

    cudaFuncSetAttribute(mma_gemm_kernel,
                         cudaFuncAttributeMaxDynamicSharedMemorySize, GEMM_SMEM);

    ln_split_kernel<<<MROWS, 256>>>(hs, lns, lnb);

    trans_split_kernel<<<dim3(16, 32), 256>>>(Wk, 512, 0, 0);
    trans_split_kernel<<<dim3(16, 32), 256>>>(Wq, 512, 0, 512 * 1024);
    trans_split_kernel<<<dim3(32, 32), 256>>>(Wv, 1024, 0, 1024 * 1024);
    trans_split_kernel<<<dim3(32, 32), 256>>>(Wo, 1024, 1, 0);

    mma_gemm_kernel<<<dim3(2048 / BN, MROWS / BM), 256, GEMM_SMEM>>>(nullptr, nullptr, 0);

    build_partial_kernel<<<dim3(BH_, NCH), 256>>>(pl);
    solve_kernel<<<BH_, 256>>>(lridge, lgamma);
    filter_kernel<<<dim3(BH_, T_ / 64), 256>>>(pl);

    mma_gemm_kernel<<<dim3(1024 / BN, MROWS / BM), 256, GEMM_SMEM>>>(out, gate, 1);
}

// round 5
// speedup vs baseline: 4.8769x; 1.2643x over previous
#include <cuda_runtime.h>
#include <cuda_bf16.h>
#include <math.h>
#include <stdint.h>

#define B_    4
#define T_    4096
#define D_    1024
#define H_    16
#define R_    32
#define DH_   64
#define BH_   64
#define MROWS 16384
#define NCH   8

// ---- mma.sync GEMM tiling ----
#define BM 128
#define BN 128
#define BK 32
#define NCHUNK 32               // D_/BK
#define ST_A_H 0
#define ST_A_L (8*1024)
#define ST_B_H (16*1024)
#define ST_B_L (24*1024)
#define STAGE  (32*1024)
#define NSTAGE 3
#define GEMM_SMEM (NSTAGE*STAGE)

// ---------------- scratch (device globals; no allocation) ----------------
__device__ __align__(128) __nv_bfloat16 g_Ah[(size_t)MROWS * D_];
__device__ __align__(128) __nv_bfloat16 g_Al[(size_t)MROWS * D_];
__device__ __align__(128) __nv_bfloat16 g_Fh[(size_t)MROWS * D_];
__device__ __align__(128) __nv_bfloat16 g_Fl[(size_t)MROWS * D_];
__device__ __align__(128) __nv_bfloat16 g_Wth[(size_t)2048 * D_];   // [n][k] KQV
__device__ __align__(128) __nv_bfloat16 g_Wtl[(size_t)2048 * D_];
__device__ __align__(128) __nv_bfloat16 g_Woth[(size_t)1024 * D_];  // [n][k] Wo
__device__ __align__(128) __nv_bfloat16 g_Wotl[(size_t)1024 * D_];
__device__ float g_K[(size_t)BH_ * T_ * R_];
__device__ float g_Q[(size_t)BH_ * T_ * R_];
__device__ float g_V[(size_t)BH_ * T_ * DH_];
__device__ float g_part[(size_t)BH_ * NCH * 4096];
__device__ float g_Tmat[(size_t)BH_ * DH_ * R_];

// ---------------- PTX helpers (baseline ISA only) ----------------
__device__ __forceinline__ uint32_t smem_u32(const void* p) {
    uint32_t a;
    asm("{ .reg .u64 t; cvta.to.shared.u64 t, %1; cvt.u32.u64 %0, t; }" : "=r"(a) : "l"(p));
    return a;
}
__device__ __forceinline__ void cp16(uint32_t dst, const void* src) {
    asm volatile("cp.async.cg.shared.global [%0], [%1], 16;" :: "r"(dst), "l"(src) : "memory");
}
__device__ __forceinline__ void cp_commit() {
    asm volatile("cp.async.commit_group;" ::: "memory");
}
template<int N> __device__ __forceinline__ void cp_wait() {
    asm volatile("cp.async.wait_group %0;" :: "n"(N) : "memory");
}
__device__ __forceinline__ void ldsm4(uint32_t* r, uint32_t addr) {
    asm volatile("ldmatrix.sync.aligned.m8n8.x4.shared.b16 {%0,%1,%2,%3}, [%4];"
                 : "=r"(r[0]), "=r"(r[1]), "=r"(r[2]), "=r"(r[3]) : "r"(addr));
}
__device__ __forceinline__ void mma16816(float* c, const uint32_t* a, const uint32_t* b) {
    asm volatile("mma.sync.aligned.m16n8k16.row.col.f32.bf16.bf16.f32 "
                 "{%0,%1,%2,%3}, {%4,%5,%6,%7}, {%8,%9}, {%0,%1,%2,%3};"
                 : "+f"(c[0]), "+f"(c[1]), "+f"(c[2]), "+f"(c[3])
                 : "r"(a[0]), "r"(a[1]), "r"(a[2]), "r"(a[3]), "r"(b[0]), "r"(b[1]));
}
// 64B-row swizzle: XOR 16B-unit (bits 4,5) with row bits 1,2 (addr bits 7,8)
__device__ __forceinline__ uint32_t swz64(uint32_t b) { return b ^ ((b >> 3) & 0x30); }

// ---------------- LayerNorm -> bf16 hi/lo ----------------
__global__ __launch_bounds__(256)
void ln_split_kernel(const float* __restrict__ x, const float* __restrict__ sc,
                     const float* __restrict__ bi)
{
    int row = blockIdx.x;
    int tid = threadIdx.x;
    const float4* xr = (const float4*)(x + (size_t)row * D_);
    float4 v = xr[tid];
    float s  = v.x + v.y + v.z + v.w;
    float ss = v.x*v.x + v.y*v.y + v.z*v.z + v.w*v.w;
    __shared__ float rs[8], rss[8];
    #pragma unroll
    for (int o = 16; o > 0; o >>= 1) {
        s  += __shfl_down_sync(0xffffffffu, s,  o);
        ss += __shfl_down_sync(0xffffffffu, ss, o);
    }
    int w = tid >> 5, l = tid & 31;
    if (l == 0) { rs[w] = s; rss[w] = ss; }
    __syncthreads();
    if (tid == 0) {
        float a = 0.f, b = 0.f;
        #pragma unroll
        for (int i = 0; i < 8; i++) { a += rs[i]; b += rss[i]; }
        rs[0] = a; rss[0] = b;
    }
    __syncthreads();
    float mu   = rs[0]  * (1.0f / D_);
    float var  = rss[0] * (1.0f / D_) - mu * mu;
    float rstd = rsqrtf(var + 1e-5f);
    float4 s4 = ((const float4*)sc)[tid];
    float4 b4 = ((const float4*)bi)[tid];
    float o0 = (v.x - mu) * rstd * s4.x + b4.x;
    float o1 = (v.y - mu) * rstd * s4.y + b4.y;
    float o2 = (v.z - mu) * rstd * s4.z + b4.z;
    float o3 = (v.w - mu) * rstd * s4.w + b4.w;
    size_t base = (size_t)row * D_ + tid * 4;
    __nv_bfloat16 h0 = __float2bfloat16(o0), h1 = __float2bfloat16(o1);
    __nv_bfloat16 h2 = __float2bfloat16(o2), h3 = __float2bfloat16(o3);
    g_Ah[base+0] = h0; g_Ah[base+1] = h1; g_Ah[base+2] = h2; g_Ah[base+3] = h3;
    g_Al[base+0] = __float2bfloat16(o0 - __bfloat162float(h0));
    g_Al[base+1] = __float2bfloat16(o1 - __bfloat162float(h1));
    g_Al[base+2] = __float2bfloat16(o2 - __bfloat162float(h2));
    g_Al[base+3] = __float2bfloat16(o3 - __bfloat162float(h3));
}

// ---------------- weight transpose + split: W[K][N] -> dst[n][k] ----------------
__global__ __launch_bounds__(256)
void trans_split_kernel(const float* __restrict__ W, int N, int sel, int dstoff)
{
    __shared__ float tile[32][33];
    __nv_bfloat16* dh = (sel == 0 ? g_Wth : g_Woth) + (size_t)dstoff;
    __nv_bfloat16* dl = (sel == 0 ? g_Wtl : g_Wotl) + (size_t)dstoff;
    int n0 = blockIdx.x * 32, k0 = blockIdx.y * 32;
    int lane = threadIdx.x & 31, wrp = threadIdx.x >> 5;
    for (int i = wrp; i < 32; i += 8)
        tile[i][lane] = W[(size_t)(k0 + i) * N + n0 + lane];
    __syncthreads();
    for (int i = wrp; i < 32; i += 8) {
        float v = tile[lane][i];
        __nv_bfloat16 h = __float2bfloat16(v);
        dh[(size_t)(n0 + i) * D_ + k0 + lane] = h;
        dl[(size_t)(n0 + i) * D_ + k0 + lane] = __float2bfloat16(v - __bfloat162float(h));
    }
}

// ---------------- split-bf16 mma.sync GEMM ----------------
// mode 0: A=g_Ah/Al [16384][1024], B=g_Wth/Wtl [2048][1024], scatter K/Q/V
//         (skips tiles whose outputs are never read: K cols for t>=P, Q cols for t<P)
// mode 1: A=g_Fh/Fl,               B=g_Woth/Wotl,            out = sigmoid(gate)*C
__global__ __launch_bounds__(256, 2)
void mma_gemm_kernel(float* __restrict__ Cout, const float* __restrict__ gate,
                     const int* __restrict__ pl, int mode)
{
    extern __shared__ __align__(1024) char sm[];
    uint32_t sbase = smem_u32(sm);

    const int tid  = threadIdx.x;
    const int lane = tid & 31;
    const int wid  = tid >> 5;
    const int wm   = wid & 3;        // m block (32 rows)
    const int wn   = wid >> 2;       // n block (64 cols)
    const int m0   = blockIdx.y * BM;
    const int ntb  = blockIdx.x * BN;

    if (mode == 0) {
        int P = *pl; if (P < 1) P = 1; if (P > T_ - 1) P = T_ - 1;
        int t0 = m0 & (T_ - 1);             // BM=128 rows share one batch, t0..t0+127
        if (ntb < 512) {                    // K region: only t < P read
            if (t0 >= P) return;
        } else if (ntb < 1024) {            // Q region: only t >= P read
            if (t0 + BM - 1 < P) return;
        }
    }

    const __nv_bfloat16* Agh = (mode == 0) ? g_Ah : g_Fh;
    const __nv_bfloat16* Agl = (mode == 0) ? g_Al : g_Fl;
    const __nv_bfloat16* Bgh = (mode == 0) ? g_Wth : g_Woth;
    const __nv_bfloat16* Bgl = (mode == 0) ? g_Wtl : g_Wotl;

    float acc[2][8][4];
    #pragma unroll
    for (int i = 0; i < 2; i++)
        #pragma unroll
        for (int j = 0; j < 8; j++)
            #pragma unroll
            for (int k = 0; k < 4; k++) acc[i][j][k] = 0.f;

    // ldmatrix per-lane address components
    const int a_r15 = lane & 15;                         // row within 16
    const int a_hi  = lane >> 4;                         // k-half
    const int b_nr  = (lane & 7) | ((lane >> 1) & 8);    // row within 16
    const int b_hi  = (lane >> 3) & 1;                   // k-half

    // loader: 512 16B-units per tensor, 2 per thread
    #define LOAD_STAGE(stg, koff)                                              \
        do {                                                                   \
            _Pragma("unroll")                                                  \
            for (int i_ = 0; i_ < 2; i_++) {                                   \
                int idx_ = tid + i_ * 256;                                     \
                int row_ = idx_ >> 2, u_ = idx_ & 3;                           \
                uint32_t d_ = swz64(row_ * 64 + u_ * 16);                      \
                size_t ka_ = (size_t)(m0 + row_) * D_ + (koff) + u_ * 8;       \
                size_t kb_ = (size_t)(ntb + row_) * D_ + (koff) + u_ * 8;      \
                cp16((stg) + ST_A_H + d_, Agh + ka_);                          \
                cp16((stg) + ST_A_L + d_, Agl + ka_);                          \
                cp16((stg) + ST_B_H + d_, Bgh + kb_);                          \
                cp16((stg) + ST_B_L + d_, Bgl + kb_);                          \
            }                                                                  \
            cp_commit();                                                       \
        } while (0)

    LOAD_STAGE(sbase, 0);
    LOAD_STAGE(sbase + STAGE, BK);

    int snext = 2;                  // stage index receiving next prefetch
    int scur  = 0;                  // stage index being consumed
    for (int c = 0; c < NCHUNK; c++) {
        if (c + 2 < NCHUNK) {
            LOAD_STAGE(sbase + snext * STAGE, (c + 2) * BK);
            cp_wait<2>();
        } else if (c + 1 < NCHUNK) {
            cp_wait<1>();
        } else {
            cp_wait<0>();
        }
        __syncthreads();

        uint32_t st = sbase + scur * STAGE;
        #pragma unroll
        for (int ks = 0; ks < 2; ks++) {
            uint32_t ah0[4], ah1[4], al0[4], al1[4];
            {
                int u = ks * 2 + a_hi;
                uint32_t off0 = swz64((wm * 32 + a_r15) * 64 + u * 16);
                uint32_t off1 = swz64((wm * 32 + 16 + a_r15) * 64 + u * 16);
                ldsm4(ah0, st + ST_A_H + off0);
                ldsm4(ah1, st + ST_A_H + off1);
                ldsm4(al0, st + ST_A_L + off0);
                ldsm4(al1, st + ST_A_L + off1);
            }
            #pragma unroll
            for (int half = 0; half < 2; half++) {
                uint32_t bh[4][2], bl[4][2];
                #pragma unroll
                for (int p = 0; p < 2; p++) {
                    int u = ks * 2 + b_hi;
                    uint32_t off = swz64((wn * 64 + half * 32 + p * 16 + b_nr) * 64 + u * 16);
                    uint32_t r[4];
                    ldsm4(r, st + ST_B_H + off);
                    bh[p*2][0] = r[0]; bh[p*2][1] = r[1];
                    bh[p*2+1][0] = r[2]; bh[p*2+1][1] = r[3];
                    ldsm4(r, st + ST_B_L + off);
                    bl[p*2][0] = r[0]; bl[p*2][1] = r[1];
                    bl[p*2+1][0] = r[2]; bl[p*2+1][1] = r[3];
                }
                #pragma unroll
                for (int f = 0; f < 4; f++) {
                    int nf = half * 4 + f;
                    mma16816(acc[0][nf], ah0, bh[f]);
                    mma16816(acc[1][nf], ah1, bh[f]);
                    mma16816(acc[0][nf], ah0, bl[f]);
                    mma16816(acc[1][nf], ah1, bl[f]);
                    mma16816(acc[0][nf], al0, bh[f]);
                    mma16816(acc[1][nf], al1, bh[f]);
                }
            }
        }
        __syncthreads();
        scur  = (scur == NSTAGE - 1) ? 0 : scur + 1;
        snext = (snext == NSTAGE - 1) ? 0 : snext + 1;
    }

    // ---- epilogue ----
    float gm = (mode == 1) ? (1.0f / (1.0f + expf(-gate[0]))) : 1.0f;
    #pragma unroll
    for (int mf = 0; mf < 2; mf++) {
        int mrow0 = m0 + wm * 32 + mf * 16 + (lane >> 2);
        #pragma unroll
        for (int nf = 0; nf < 8; nf++) {
            int n = ntb + wn * 64 + nf * 8 + (lane & 3) * 2;
            #pragma unroll
            for (int rh = 0; rh < 2; rh++) {
                int m = mrow0 + rh * 8;
                float2 v;
                v.x = gm * acc[mf][nf][rh * 2 + 0];
                v.y = gm * acc[mf][nf][rh * 2 + 1];
                if (mode == 1) {
                    *(float2*)(Cout + (size_t)m * 1024 + n) = v;
                } else {
                    int b = m >> 12, t = m & (T_ - 1);
                    float* dst;
                    if (n < 512) {
                        dst = g_K + (((size_t)(b * H_ + (n >> 5))) * T_ + t) * R_ + (n & 31);
                    } else if (n < 1024) {
                        int n2 = n - 512;
                        dst = g_Q + (((size_t)(b * H_ + (n2 >> 5))) * T_ + t) * R_ + (n2 & 31);
                    } else {
                        int nv = n - 1024;
                        dst = g_V + (((size_t)(b * H_ + (nv >> 6))) * T_ + t) * DH_ + (nv & 63);
                    }
                    *(float2*)dst = v;
                }
            }
        }
    }
}

// ---------------- partial G/M/Cv accumulation ----------------
__global__ __launch_bounds__(256)
void build_partial_kernel(const int* __restrict__ pl)
{
    int bh = blockIdx.x;
    int chunk = blockIdx.y;
    int P = *pl; if (P < 1) P = 1; if (P > T_ - 1) P = T_ - 1;
    int ch = (P + NCH - 1) / NCH;
    int lo = chunk * ch;
    int hi = min(lo + ch, P);

    const float* K = g_K + (size_t)bh * T_ * R_;
    const float* V = g_V + (size_t)bh * T_ * DH_;
    __shared__ __align__(16) float Ks[65][32];
    __shared__ __align__(16) float Vs[64][64];

    int tid = threadIdx.x;
    int r  = tid & 31, sg = tid >> 5;
    int d  = tid & 63, rg = tid >> 6;
    float gacc[4] = {0, 0, 0, 0};
    float macc[4] = {0, 0, 0, 0};
    float cacc[8] = {0, 0, 0, 0, 0, 0, 0, 0};

    for (int t0 = lo; t0 < hi; t0 += 64) {
        int nrows = min(64, hi - t0);
        for (int idx = tid; idx < (nrows + 1) * 8; idx += 256) {
            int rr = idx >> 3, cq = (idx & 7) * 4;
            *(float4*)&Ks[rr][cq] = *(const float4*)&K[(size_t)(t0 + rr) * R_ + cq];
        }
        for (int idx = tid; idx < nrows * 16; idx += 256) {
            int rr = idx >> 4, cq = (idx & 15) * 4;
            *(float4*)&Vs[rr][cq] = *(const float4*)&V[(size_t)(t0 + rr) * DH_ + cq];
        }
        __syncthreads();
        for (int tt = 0; tt < nrows; tt++) {
            int t = t0 + tt;
            float kr  = Ks[tt][r];
            float ks0 = Ks[tt][sg * 4 + 0], ks1 = Ks[tt][sg * 4 + 1];
            float ks2 = Ks[tt][sg * 4 + 2], ks3 = Ks[tt][sg * 4 + 3];
            gacc[0] += kr * ks0; gacc[1] += kr * ks1;
            gacc[2] += kr * ks2; gacc[3] += kr * ks3;
            if (t < P - 1) {
                float kn = Ks[tt + 1][r];
                macc[0] += kn * ks0; macc[1] += kn * ks1;
                macc[2] += kn * ks2; macc[3] += kn * ks3;
            }
            float vv = Vs[tt][d];
            #pragma unroll
            for (int j = 0; j < 8; j++) cacc[j] += vv * Ks[tt][rg * 8 + j];
        }
        __syncthreads();
    }
    float* out = g_part + ((size_t)bh * NCH + chunk) * 4096;
    #pragma unroll
    for (int j = 0; j < 4; j++) {
        out[r * 32 + sg * 4 + j]        = gacc[j];
        out[1024 + r * 32 + sg * 4 + j] = macc[j];
    }
    #pragma unroll
    for (int j = 0; j < 8; j++) out[2048 + d * 32 + rg * 8 + j] = cacc[j];
}

// ---------------- per-head solve ----------------
#define MM32(Cm, Am, Bm)                                                     \
    do {                                                                     \
        for (int e = tid; e < 1024; e += 256) {                              \
            int rr = e >> 5, cc = e & 31; float s = 0.f;                     \
            _Pragma("unroll") for (int k2 = 0; k2 < 32; k2++)                \
                s += Am[rr][k2] * Bm[k2][cc];                                \
            Cm[rr][cc] = s;                                                  \
        }                                                                    \
        __syncthreads();                                                     \
    } while (0)

__global__ __launch_bounds__(256)
void solve_kernel(const float* __restrict__ lridge, const float* __restrict__ lgamma)
{
    __shared__ float sG[32][33], sM[32][33], sL[32][33], sLi[32][33];
    __shared__ float sAw[32][33], sT[32][33];
    __shared__ float sCv[64][33], sBv[64][33];
    __shared__ float sScale;

    int bh = blockIdx.x;
    int tid = threadIdx.x;

    const float* base = g_part + (size_t)bh * NCH * 4096;
    for (int idx = tid; idx < 4096; idx += 256) {
        float s = 0.f;
        #pragma unroll
        for (int c = 0; c < NCH; c++) s += base[(size_t)c * 4096 + idx];
        if (idx < 1024)      sG[idx >> 5][idx & 31] = s;
        else if (idx < 2048) sM[(idx - 1024) >> 5][idx & 31] = s;
        else { int e = idx - 2048; sCv[e >> 5][e & 31] = s; }
    }
    __syncthreads();
    if (tid < 32) sG[tid][tid] += expf(lridge[0]);
    __syncthreads();

    if (tid < 32) {
        int i = tid;
        for (int j = 0; j < 32; j++) {
            if (i == j) {
                float s = sG[j][j];
                for (int k = 0; k < j; k++) s -= sL[j][k] * sL[j][k];
                sL[j][j] = sqrtf(fmaxf(s, 1e-30f));
            }
            __syncwarp();
            if (i > j) {
                float s = sG[i][j];
                for (int k = 0; k < j; k++) s -= sL[i][k] * sL[j][k];
                sL[i][j] = s / sL[j][j];
            } else if (i < j) {
                sL[i][j] = 0.f;
            }
            __syncwarp();
        }
        int j = tid;
        for (int i2 = 0; i2 < 32; i2++) sLi[i2][j] = 0.f;
        for (int i2 = j; i2 < 32; i2++) {
            float s = (i2 == j) ? 1.f : 0.f;
            for (int k = j; k < i2; k++) s -= sL[i2][k] * sLi[k][j];
            sLi[i2][j] = s / sL[i2][i2];
        }
    }
    __syncthreads();

    MM32(sT, sLi, sM);
    for (int e = tid; e < 1024; e += 256) {
        int rr = e >> 5, cc = e & 31; float s = 0.f;
        #pragma unroll
        for (int k2 = 0; k2 < 32; k2++) s += sT[rr][k2] * sLi[cc][k2];
        sAw[rr][cc] = s;
    }
    __syncthreads();

    if (tid < 32) {
        int i = tid;
        float v = 1.0f + 0.37f * (float)i;
        float sig = 0.f;
        for (int it = 0; it < 200; it++) {
            float u = 0.f;
            #pragma unroll
            for (int k = 0; k < 32; k++) u += sAw[i][k] * __shfl_sync(0xffffffffu, v, k);
            float w = 0.f;
            #pragma unroll
            for (int k = 0; k < 32; k++) w += sAw[k][i] * __shfl_sync(0xffffffffu, u, k);
            float n2 = w * w;
            #pragma unroll
            for (int o = 16; o > 0; o >>= 1) n2 += __shfl_xor_sync(0xffffffffu, n2, o);
            float nrm = sqrtf(n2);
            v = w / fmaxf(nrm, 1e-30f);
            sig = sqrtf(nrm);
        }
        if (i == 0) {
            float gamma = expf(lgamma[0]);
            float gc = fminf(gamma, 1.0f);
            float s0 = fmaxf(sig, 1e-8f);
            sScale = gc / fmaxf(s0, 1.0f);
        }
    }
    __syncthreads();
    float scl = sScale;
    for (int e = tid; e < 1024; e += 256) sAw[e >> 5][e & 31] *= scl;
    __syncthreads();

    MM32(sT, sAw, sAw);
    MM32(sM, sT, sT);
    MM32(sG, sM, sLi);
    MM32(sT, sL, sG);

    for (int e = tid; e < 2048; e += 256) {
        int dd = e >> 5, rr = e & 31; float s = 0.f;
        #pragma unroll
        for (int k2 = 0; k2 < 32; k2++) s += sCv[dd][k2] * sLi[rr][k2];
        sBv[dd][rr] = s;
    }
    __syncthreads();
    for (int e = tid; e < 2048; e += 256) {
        int dd = e >> 5, rr = e & 31; float s = 0.f;
        #pragma unroll
        for (int k2 = 0; k2 < 32; k2++) s += sBv[dd][k2] * sLi[k2][rr];
        sCv[dd][rr] = s;
    }
    __syncthreads();

    float* tm = g_Tmat + (size_t)bh * DH_ * R_;
    for (int e = tid; e < 2048; e += 256) {
        int dd = e >> 5, rr = e & 31; float s = 0.f;
        #pragma unroll
        for (int k2 = 0; k2 < 32; k2++) s += sCv[dd][k2] * sT[k2][rr];
        tm[dd * R_ + rr] = s;
    }
}

// ---------------- filter: F[b,t,h*64+d] = Tmat @ (k or q), split bf16 ----------------
__global__ __launch_bounds__(256)
void filter_kernel(const int* __restrict__ pl)
{
    int bh = blockIdx.x;
    int t0 = blockIdx.y * 64;
    int P = *pl; if (P < 1) P = 1; if (P > T_ - 1) P = T_ - 1;

    __shared__ float Tm[DH_][R_ + 1];
    __shared__ float Qs[64][R_];
    int tid = threadIdx.x;

    for (int idx = tid; idx < DH_ * R_; idx += 256)
        Tm[idx >> 5][idx & 31] = g_Tmat[(size_t)bh * DH_ * R_ + idx];
    for (int idx = tid; idx < 64 * R_; idx += 256) {
        int tt = idx >> 5, rr = idx & 31;
        int t = t0 + tt;
        const float* src = (t < P) ? g_K : g_Q;
        Qs[tt][rr] = src[((size_t)bh * T_ + t) * R_ + rr];
    }
    __syncthreads();

    int d  = tid & 63;
    int tg = tid >> 6;
    float tm[R_];
    #pragma unroll
    for (int r = 0; r < R_; r++) tm[r] = Tm[d][r];
    int b = bh >> 4, h = bh & 15;
    #pragma unroll
    for (int k = 0; k < 16; k++) {
        int tt = tg * 16 + k;
        float s = 0.f;
        #pragma unroll
        for (int r = 0; r < R_; r++) s += tm[r] * Qs[tt][r];
        size_t idx = ((size_t)(b * T_ + t0 + tt)) * D_ + h * DH_ + d;
        __nv_bfloat16 hv = __float2bfloat16(s);
        g_Fh[idx] = hv;
        g_Fl[idx] = __float2bfloat16(s - __bfloat162float(hv));
    }
}

// ---------------- launcher ----------------
extern "C" void kernel_launch(void* const* d_in, const int* in_sizes, int n_in,
                              void* d_out, int out_size)
{
    const float* hs     = (const float*)d_in[0];
    const float* Wk     = (const float*)d_in[1];
    const float* Wq     = (const float*)d_in[2];
    const float* Wv     = (const float*)d_in[3];
    const float* Wo     = (const float*)d_in[4];
    const float* lns    = (const float*)d_in[5];
    const float* lnb    = (const float*)d_in[6];
    const float* gate   = (const float*)d_in[7];
    const float* lridge = (const float*)d_in[8];
    const float* lgamma = (const float*)d_in[9];
    const int*   pl     = (const int*)d_in[10];
    float* out = (float*)d_out;

    cudaFuncSetAttribute(mma_gemm_kernel,
                         cudaFuncAttributeMaxDynamicSharedMemorySize, GEMM_SMEM);

    ln_split_kernel<<<MROWS, 256>>>(hs, lns, lnb);

    trans_split_kernel<<<dim3(16, 32), 256>>>(Wk, 512, 0, 0);
    trans_split_kernel<<<dim3(16, 32), 256>>>(Wq, 512, 0, 512 * 1024);
    trans_split_kernel<<<dim3(32, 32), 256>>>(Wv, 1024, 0, 1024 * 1024);
    trans_split_kernel<<<dim3(32, 32), 256>>>(Wo, 1024, 1, 0);

    mma_gemm_kernel<<<dim3(2048 / BN, MROWS / BM), 256, GEMM_SMEM>>>(nullptr, nullptr, pl, 0);

    build_partial_kernel<<<dim3(BH_, NCH), 256>>>(pl);
    solve_kernel<<<BH_, 256>>>(lridge, lgamma);
    filter_kernel<<<dim3(BH_, T_ / 64), 256>>>(pl);

    mma_gemm_kernel<<<dim3(1024 / BN, MROWS / BM), 256, GEMM_SMEM>>>(out, gate, pl, 1);
}

// round 6
// speedup vs baseline: 6.6917x; 1.3721x over previous
#include <cuda_runtime.h>
#include <cuda_bf16.h>
#include <math.h>
#include <stdint.h>

#define B_    4
#define T_    4096
#define D_    1024
#define H_    16
#define R_    32
#define DH_   64
#define BH_   64
#define MROWS 16384
#define NCH   8
#define ZK    512              // Z feature dim (H_*R_)

// ---- mma.sync GEMM tiling ----
#define BM 128
#define BN 128
#define BK 32
#define ST_A_H 0
#define ST_A_L (8*1024)
#define ST_B_H (16*1024)
#define ST_B_L (24*1024)
#define STAGE  (32*1024)
#define NSTAGE 3
#define GEMM_SMEM (NSTAGE*STAGE)

// ---------------- scratch (device globals; no allocation) ----------------
__device__ __align__(128) __nv_bfloat16 g_Ah[(size_t)MROWS * D_];
__device__ __align__(128) __nv_bfloat16 g_Al[(size_t)MROWS * D_];
__device__ __align__(128) __nv_bfloat16 g_Wth[(size_t)2048 * D_];   // [n][k] KQV
__device__ __align__(128) __nv_bfloat16 g_Wtl[(size_t)2048 * D_];
__device__ __align__(128) __nv_bfloat16 g_Woth[(size_t)1024 * D_];  // [n][k] Wo
__device__ __align__(128) __nv_bfloat16 g_Wotl[(size_t)1024 * D_];
__device__ __align__(128) __nv_bfloat16 g_Zh[(size_t)MROWS * ZK];   // token z, hi
__device__ __align__(128) __nv_bfloat16 g_Zl[(size_t)MROWS * ZK];   // token z, lo
__device__ __align__(128) __nv_bfloat16 g_W2h[(size_t)B_ * 1024 * ZK]; // [b][n][k]
__device__ __align__(128) __nv_bfloat16 g_W2l[(size_t)B_ * 1024 * ZK];
__device__ float g_K[(size_t)BH_ * T_ * R_];
__device__ float g_V[(size_t)BH_ * T_ * DH_];
__device__ float g_part[(size_t)BH_ * NCH * 4096];
__device__ float g_Tmat[(size_t)BH_ * DH_ * R_];

// ---------------- PTX helpers (baseline ISA only) ----------------
__device__ __forceinline__ uint32_t smem_u32(const void* p) {
    uint32_t a;
    asm("{ .reg .u64 t; cvta.to.shared.u64 t, %1; cvt.u32.u64 %0, t; }" : "=r"(a) : "l"(p));
    return a;
}
__device__ __forceinline__ void cp16(uint32_t dst, const void* src) {
    asm volatile("cp.async.cg.shared.global [%0], [%1], 16;" :: "r"(dst), "l"(src) : "memory");
}
__device__ __forceinline__ void cp_commit() {
    asm volatile("cp.async.commit_group;" ::: "memory");
}
template<int N> __device__ __forceinline__ void cp_wait() {
    asm volatile("cp.async.wait_group %0;" :: "n"(N) : "memory");
}
__device__ __forceinline__ void ldsm4(uint32_t* r, uint32_t addr) {
    asm volatile("ldmatrix.sync.aligned.m8n8.x4.shared.b16 {%0,%1,%2,%3}, [%4];"
                 : "=r"(r[0]), "=r"(r[1]), "=r"(r[2]), "=r"(r[3]) : "r"(addr));
}
__device__ __forceinline__ void mma16816(float* c, const uint32_t* a, const uint32_t* b) {
    asm volatile("mma.sync.aligned.m16n8k16.row.col.f32.bf16.bf16.f32 "
                 "{%0,%1,%2,%3}, {%4,%5,%6,%7}, {%8,%9}, {%0,%1,%2,%3};"
                 : "+f"(c[0]), "+f"(c[1]), "+f"(c[2]), "+f"(c[3])
                 : "r"(a[0]), "r"(a[1]), "r"(a[2]), "r"(a[3]), "r"(b[0]), "r"(b[1]));
}
// 64B-row swizzle
__device__ __forceinline__ uint32_t swz64(uint32_t b) { return b ^ ((b >> 3) & 0x30); }

// ---------------- LayerNorm -> bf16 hi/lo ----------------
__global__ __launch_bounds__(256)
void ln_split_kernel(const float* __restrict__ x, const float* __restrict__ sc,
                     const float* __restrict__ bi)
{
    int row = blockIdx.x;
    int tid = threadIdx.x;
    const float4* xr = (const float4*)(x + (size_t)row * D_);
    float4 v = xr[tid];
    float s  = v.x + v.y + v.z + v.w;
    float ss = v.x*v.x + v.y*v.y + v.z*v.z + v.w*v.w;
    __shared__ float rs[8], rss[8];
    #pragma unroll
    for (int o = 16; o > 0; o >>= 1) {
        s  += __shfl_down_sync(0xffffffffu, s,  o);
        ss += __shfl_down_sync(0xffffffffu, ss, o);
    }
    int w = tid >> 5, l = tid & 31;
    if (l == 0) { rs[w] = s; rss[w] = ss; }
    __syncthreads();
    if (tid == 0) {
        float a = 0.f, b = 0.f;
        #pragma unroll
        for (int i = 0; i < 8; i++) { a += rs[i]; b += rss[i]; }
        rs[0] = a; rss[0] = b;
    }
    __syncthreads();
    float mu   = rs[0]  * (1.0f / D_);
    float var  = rss[0] * (1.0f / D_) - mu * mu;
    float rstd = rsqrtf(var + 1e-5f);
    float4 s4 = ((const float4*)sc)[tid];
    float4 b4 = ((const float4*)bi)[tid];
    float o0 = (v.x - mu) * rstd * s4.x + b4.x;
    float o1 = (v.y - mu) * rstd * s4.y + b4.y;
    float o2 = (v.z - mu) * rstd * s4.z + b4.z;
    float o3 = (v.w - mu) * rstd * s4.w + b4.w;
    size_t base = (size_t)row * D_ + tid * 4;
    __nv_bfloat16 h0 = __float2bfloat16(o0), h1 = __float2bfloat16(o1);
    __nv_bfloat16 h2 = __float2bfloat16(o2), h3 = __float2bfloat16(o3);
    g_Ah[base+0] = h0; g_Ah[base+1] = h1; g_Ah[base+2] = h2; g_Ah[base+3] = h3;
    g_Al[base+0] = __float2bfloat16(o0 - __bfloat162float(h0));
    g_Al[base+1] = __float2bfloat16(o1 - __bfloat162float(h1));
    g_Al[base+2] = __float2bfloat16(o2 - __bfloat162float(h2));
    g_Al[base+3] = __float2bfloat16(o3 - __bfloat162float(h3));
}

// ---------------- weight transpose + split: W[K][N] -> dst[n][k] ----------------
__global__ __launch_bounds__(256)
void trans_split_kernel(const float* __restrict__ W, int N, int sel, int dstoff)
{
    __shared__ float tile[32][33];
    __nv_bfloat16* dh = (sel == 0 ? g_Wth : g_Woth) + (size_t)dstoff;
    __nv_bfloat16* dl = (sel == 0 ? g_Wtl : g_Wotl) + (size_t)dstoff;
    int n0 = blockIdx.x * 32, k0 = blockIdx.y * 32;
    int lane = threadIdx.x & 31, wrp = threadIdx.x >> 5;
    for (int i = wrp; i < 32; i += 8)
        tile[i][lane] = W[(size_t)(k0 + i) * N + n0 + lane];
    __syncthreads();
    for (int i = wrp; i < 32; i += 8) {
        float v = tile[lane][i];
        __nv_bfloat16 h = __float2bfloat16(v);
        dh[(size_t)(n0 + i) * D_ + k0 + lane] = h;
        dl[(size_t)(n0 + i) * D_ + k0 + lane] = __float2bfloat16(v - __bfloat162float(h));
    }
}

// ---------------- split-bf16 mma.sync GEMM ----------------
// mode 0: A=g_Ah/Al [16384][1024], B=g_Wth/Wtl [2048][1024]
//         skips dead tiles (K & V for t>=P, Q for t<P); epilogue: g_K, g_V, Z
// mode 1: A=g_Zh/Zl [16384][512],  B=g_W2h/W2l (per-batch), out = sigmoid(gate)*C
__global__ __launch_bounds__(256, 2)
void mma_gemm_kernel(float* __restrict__ Cout, const float* __restrict__ gate,
                     const int* __restrict__ pl, int mode)
{
    extern __shared__ __align__(1024) char sm[];
    uint32_t sbase = smem_u32(sm);

    const int tid  = threadIdx.x;
    const int lane = tid & 31;
    const int wid  = tid >> 5;
    const int wm   = wid & 3;        // m block (32 rows)
    const int wn   = wid >> 2;       // n block (64 cols)
    const int m0   = blockIdx.y * BM;
    const int ntb  = blockIdx.x * BN;

    int P = *pl; if (P < 1) P = 1; if (P > T_ - 1) P = T_ - 1;

    if (mode == 0) {
        int t0 = m0 & (T_ - 1);             // BM=128 rows share one batch
        if (ntb < 512) {                    // K region: only t < P read
            if (t0 >= P) return;
        } else if (ntb < 1024) {            // Q region: only t >= P read
            if (t0 + BM - 1 < P) return;
        } else {                            // V region: only t < P read
            if (t0 >= P) return;
        }
    }

    const __nv_bfloat16* Agh;
    const __nv_bfloat16* Agl;
    const __nv_bfloat16* Bgh;
    const __nv_bfloat16* Bgl;
    int lda, kch;
    if (mode == 0) {
        Agh = g_Ah; Agl = g_Al; Bgh = g_Wth; Bgl = g_Wtl;
        lda = D_; kch = D_ / BK;
    } else {
        size_t boff = (size_t)(m0 >> 12) * 1024 * ZK;
        Agh = g_Zh; Agl = g_Zl; Bgh = g_W2h + boff; Bgl = g_W2l + boff;
        lda = ZK; kch = ZK / BK;
    }

    float acc[2][8][4];
    #pragma unroll
    for (int i = 0; i < 2; i++)
        #pragma unroll
        for (int j = 0; j < 8; j++)
            #pragma unroll
            for (int k = 0; k < 4; k++) acc[i][j][k] = 0.f;

    const int a_r15 = lane & 15;
    const int a_hi  = lane >> 4;
    const int b_nr  = (lane & 7) | ((lane >> 1) & 8);
    const int b_hi  = (lane >> 3) & 1;

    // loader: 512 16B-units per tensor, 2 per thread
    #define LOAD_STAGE(stg, koff)                                              \
        do {                                                                   \
            _Pragma("unroll")                                                  \
            for (int i_ = 0; i_ < 2; i_++) {                                   \
                int idx_ = tid + i_ * 256;                                     \
                int row_ = idx_ >> 2, u_ = idx_ & 3;                           \
                uint32_t d_ = swz64(row_ * 64 + u_ * 16);                      \
                size_t ka_ = (size_t)(m0 + row_) * lda + (koff) + u_ * 8;      \
                size_t kb_ = (size_t)(ntb + row_) * lda + (koff) + u_ * 8;     \
                cp16((stg) + ST_A_H + d_, Agh + ka_);                          \
                cp16((stg) + ST_A_L + d_, Agl + ka_);                          \
                cp16((stg) + ST_B_H + d_, Bgh + kb_);                          \
                cp16((stg) + ST_B_L + d_, Bgl + kb_);                          \
            }                                                                  \
            cp_commit();                                                       \
        } while (0)

    LOAD_STAGE(sbase, 0);
    LOAD_STAGE(sbase + STAGE, BK);

    int snext = 2;
    int scur  = 0;
    for (int c = 0; c < kch; c++) {
        if (c + 2 < kch) {
            LOAD_STAGE(sbase + snext * STAGE, (c + 2) * BK);
            cp_wait<2>();
        } else if (c + 1 < kch) {
            cp_wait<1>();
        } else {
            cp_wait<0>();
        }
        __syncthreads();

        uint32_t st = sbase + scur * STAGE;
        #pragma unroll
        for (int ks = 0; ks < 2; ks++) {
            uint32_t ah0[4], ah1[4], al0[4], al1[4];
            {
                int u = ks * 2 + a_hi;
                uint32_t off0 = swz64((wm * 32 + a_r15) * 64 + u * 16);
                uint32_t off1 = swz64((wm * 32 + 16 + a_r15) * 64 + u * 16);
                ldsm4(ah0, st + ST_A_H + off0);
                ldsm4(ah1, st + ST_A_H + off1);
                ldsm4(al0, st + ST_A_L + off0);
                ldsm4(al1, st + ST_A_L + off1);
            }
            #pragma unroll
            for (int half = 0; half < 2; half++) {
                uint32_t bh[4][2], bl[4][2];
                #pragma unroll
                for (int p = 0; p < 2; p++) {
                    int u = ks * 2 + b_hi;
                    uint32_t off = swz64((wn * 64 + half * 32 + p * 16 + b_nr) * 64 + u * 16);
                    uint32_t r[4];
                    ldsm4(r, st + ST_B_H + off);
                    bh[p*2][0] = r[0]; bh[p*2][1] = r[1];
                    bh[p*2+1][0] = r[2]; bh[p*2+1][1] = r[3];
                    ldsm4(r, st + ST_B_L + off);
                    bl[p*2][0] = r[0]; bl[p*2][1] = r[1];
                    bl[p*2+1][0] = r[2]; bl[p*2+1][1] = r[3];
                }
                #pragma unroll
                for (int f = 0; f < 4; f++) {
                    int nf = half * 4 + f;
                    mma16816(acc[0][nf], ah0, bh[f]);
                    mma16816(acc[1][nf], ah1, bh[f]);
                    mma16816(acc[0][nf], ah0, bl[f]);
                    mma16816(acc[1][nf], ah1, bl[f]);
                    mma16816(acc[0][nf], al0, bh[f]);
                    mma16816(acc[1][nf], al1, bh[f]);
                }
            }
        }
        __syncthreads();
        scur  = (scur == NSTAGE - 1) ? 0 : scur + 1;
        snext = (snext == NSTAGE - 1) ? 0 : snext + 1;
    }

    // ---- epilogue ----
    float gm = (mode == 1) ? (1.0f / (1.0f + expf(-gate[0]))) : 1.0f;
    #pragma unroll
    for (int mf = 0; mf < 2; mf++) {
        int mrow0 = m0 + wm * 32 + mf * 16 + (lane >> 2);
        #pragma unroll
        for (int nf = 0; nf < 8; nf++) {
            int n = ntb + wn * 64 + nf * 8 + (lane & 3) * 2;
            #pragma unroll
            for (int rh = 0; rh < 2; rh++) {
                int m = mrow0 + rh * 8;
                float2 v;
                v.x = gm * acc[mf][nf][rh * 2 + 0];
                v.y = gm * acc[mf][nf][rh * 2 + 1];
                if (mode == 1) {
                    *(float2*)(Cout + (size_t)m * 1024 + n) = v;
                } else {
                    int b = m >> 12, t = m & (T_ - 1);
                    if (n < 1024) {
                        // z emission (split bf16) for the output GEMM
                        int zc = (n < 512) ? n : (n - 512);
                        bool emit = (n < 512) ? (t < P) : (t >= P);
                        if (emit) {
                            __nv_bfloat162 hv, lv;
                            hv.x = __float2bfloat16(v.x);
                            hv.y = __float2bfloat16(v.y);
                            lv.x = __float2bfloat16(v.x - __bfloat162float(hv.x));
                            lv.y = __float2bfloat16(v.y - __bfloat162float(hv.y));
                            *(__nv_bfloat162*)(g_Zh + (size_t)m * ZK + zc) = hv;
                            *(__nv_bfloat162*)(g_Zl + (size_t)m * ZK + zc) = lv;
                        }
                        if (n < 512) {
                            float* dst = g_K + (((size_t)(b * H_ + (n >> 5))) * T_ + t) * R_ + (n & 31);
                            *(float2*)dst = v;
                        }
                    } else {
                        int nv = n - 1024;
                        float* dst = g_V + (((size_t)(b * H_ + (nv >> 6))) * T_ + t) * DH_ + (nv & 63);
                        *(float2*)dst = v;
                    }
                }
            }
        }
    }
}

// ---------------- partial G/M/Cv accumulation ----------------
__global__ __launch_bounds__(256)
void build_partial_kernel(const int* __restrict__ pl)
{
    int bh = blockIdx.x;
    int chunk = blockIdx.y;
    int P = *pl; if (P < 1) P = 1; if (P > T_ - 1) P = T_ - 1;
    int ch = (P + NCH - 1) / NCH;
    int lo = chunk * ch;
    int hi = min(lo + ch, P);

    const float* K = g_K + (size_t)bh * T_ * R_;
    const float* V = g_V + (size_t)bh * T_ * DH_;
    __shared__ __align__(16) float Ks[65][32];
    __shared__ __align__(16) float Vs[64][64];

    int tid = threadIdx.x;
    int r  = tid & 31, sg = tid >> 5;
    int d  = tid & 63, rg = tid >> 6;
    float gacc[4] = {0, 0, 0, 0};
    float macc[4] = {0, 0, 0, 0};
    float cacc[8] = {0, 0, 0, 0, 0, 0, 0, 0};

    for (int t0 = lo; t0 < hi; t0 += 64) {
        int nrows = min(64, hi - t0);
        for (int idx = tid; idx < (nrows + 1) * 8; idx += 256) {
            int rr = idx >> 3, cq = (idx & 7) * 4;
            *(float4*)&Ks[rr][cq] = *(const float4*)&K[(size_t)(t0 + rr) * R_ + cq];
        }
        for (int idx = tid; idx < nrows * 16; idx += 256) {
            int rr = idx >> 4, cq = (idx & 15) * 4;
            *(float4*)&Vs[rr][cq] = *(const float4*)&V[(size_t)(t0 + rr) * DH_ + cq];
        }
        __syncthreads();
        for (int tt = 0; tt < nrows; tt++) {
            int t = t0 + tt;
            float kr  = Ks[tt][r];
            float ks0 = Ks[tt][sg * 4 + 0], ks1 = Ks[tt][sg * 4 + 1];
            float ks2 = Ks[tt][sg * 4 + 2], ks3 = Ks[tt][sg * 4 + 3];
            gacc[0] += kr * ks0; gacc[1] += kr * ks1;
            gacc[2] += kr * ks2; gacc[3] += kr * ks3;
            if (t < P - 1) {
                float kn = Ks[tt + 1][r];
                macc[0] += kn * ks0; macc[1] += kn * ks1;
                macc[2] += kn * ks2; macc[3] += kn * ks3;
            }
            float vv = Vs[tt][d];
            #pragma unroll
            for (int j = 0; j < 8; j++) cacc[j] += vv * Ks[tt][rg * 8 + j];
        }
        __syncthreads();
    }
    float* out = g_part + ((size_t)bh * NCH + chunk) * 4096;
    #pragma unroll
    for (int j = 0; j < 4; j++) {
        out[r * 32 + sg * 4 + j]        = gacc[j];
        out[1024 + r * 32 + sg * 4 + j] = macc[j];
    }
    #pragma unroll
    for (int j = 0; j < 8; j++) out[2048 + d * 32 + rg * 8 + j] = cacc[j];
}

// ---------------- per-head solve ----------------
#define MM32(Cm, Am, Bm)                                                     \
    do {                                                                     \
        for (int e = tid; e < 1024; e += 256) {                              \
            int rr = e >> 5, cc = e & 31; float s = 0.f;                     \
            _Pragma("unroll") for (int k2 = 0; k2 < 32; k2++)                \
                s += Am[rr][k2] * Bm[k2][cc];                                \
            Cm[rr][cc] = s;                                                  \
        }                                                                    \
        __syncthreads();                                                     \
    } while (0)

__global__ __launch_bounds__(256)
void solve_kernel(const float* __restrict__ lridge, const float* __restrict__ lgamma)
{
    __shared__ float sG[32][33], sM[32][33], sL[32][33], sLi[32][33];
    __shared__ float sAw[32][33], sT[32][33];
    __shared__ float sCv[64][33], sBv[64][33];
    __shared__ float sScale;

    int bh = blockIdx.x;
    int tid = threadIdx.x;

    const float* base = g_part + (size_t)bh * NCH * 4096;
    for (int idx = tid; idx < 4096; idx += 256) {
        float s = 0.f;
        #pragma unroll
        for (int c = 0; c < NCH; c++) s += base[(size_t)c * 4096 + idx];
        if (idx < 1024)      sG[idx >> 5][idx & 31] = s;
        else if (idx < 2048) sM[(idx - 1024) >> 5][idx & 31] = s;
        else { int e = idx - 2048; sCv[e >> 5][e & 31] = s; }
    }
    __syncthreads();
    if (tid < 32) sG[tid][tid] += expf(lridge[0]);
    __syncthreads();

    if (tid < 32) {
        int i = tid;
        for (int j = 0; j < 32; j++) {
            if (i == j) {
                float s = sG[j][j];
                for (int k = 0; k < j; k++) s -= sL[j][k] * sL[j][k];
                sL[j][j] = sqrtf(fmaxf(s, 1e-30f));
            }
            __syncwarp();
            if (i > j) {
                float s = sG[i][j];
                for (int k = 0; k < j; k++) s -= sL[i][k] * sL[j][k];
                sL[i][j] = s / sL[j][j];
            } else if (i < j) {
                sL[i][j] = 0.f;
            }
            __syncwarp();
        }
        int j = tid;
        for (int i2 = 0; i2 < 32; i2++) sLi[i2][j] = 0.f;
        for (int i2 = j; i2 < 32; i2++) {
            float s = (i2 == j) ? 1.f : 0.f;
            for (int k = j; k < i2; k++) s -= sL[i2][k] * sLi[k][j];
            sLi[i2][j] = s / sL[i2][i2];
        }
    }
    __syncthreads();

    MM32(sT, sLi, sM);
    for (int e = tid; e < 1024; e += 256) {
        int rr = e >> 5, cc = e & 31; float s = 0.f;
        #pragma unroll
        for (int k2 = 0; k2 < 32; k2++) s += sT[rr][k2] * sLi[cc][k2];
        sAw[rr][cc] = s;
    }
    __syncthreads();

    if (tid < 32) {
        int i = tid;
        float v = 1.0f + 0.37f * (float)i;
        float sig = 0.f;
        for (int it = 0; it < 200; it++) {
            float u = 0.f;
            #pragma unroll
            for (int k = 0; k < 32; k++) u += sAw[i][k] * __shfl_sync(0xffffffffu, v, k);
            float w = 0.f;
            #pragma unroll
            for (int k = 0; k < 32; k++) w += sAw[k][i] * __shfl_sync(0xffffffffu, u, k);
            float n2 = w * w;
            #pragma unroll
            for (int o = 16; o > 0; o >>= 1) n2 += __shfl_xor_sync(0xffffffffu, n2, o);
            float nrm = sqrtf(n2);
            v = w / fmaxf(nrm, 1e-30f);
            sig = sqrtf(nrm);
        }
        if (i == 0) {
            float gamma = expf(lgamma[0]);
            float gc = fminf(gamma, 1.0f);
            float s0 = fmaxf(sig, 1e-8f);
            sScale = gc / fmaxf(s0, 1.0f);
        }
    }
    __syncthreads();
    float scl = sScale;
    for (int e = tid; e < 1024; e += 256) sAw[e >> 5][e & 31] *= scl;
    __syncthreads();

    MM32(sT, sAw, sAw);
    MM32(sM, sT, sT);
    MM32(sG, sM, sLi);
    MM32(sT, sL, sG);

    for (int e = tid; e < 2048; e += 256) {
        int dd = e >> 5, rr = e & 31; float s = 0.f;
        #pragma unroll
        for (int k2 = 0; k2 < 32; k2++) s += sCv[dd][k2] * sLi[rr][k2];
        sBv[dd][rr] = s;
    }
    __syncthreads();
    for (int e = tid; e < 2048; e += 256) {
        int dd = e >> 5, rr = e & 31; float s = 0.f;
        #pragma unroll
        for (int k2 = 0; k2 < 32; k2++) s += sBv[dd][k2] * sLi[k2][rr];
        sCv[dd][rr] = s;
    }
    __syncthreads();

    float* tm = g_Tmat + (size_t)bh * DH_ * R_;
    for (int e = tid; e < 2048; e += 256) {
        int dd = e >> 5, rr = e & 31; float s = 0.f;
        #pragma unroll
        for (int k2 = 0; k2 < 32; k2++) s += sCv[dd][k2] * sT[k2][rr];
        tm[dd * R_ + rr] = s;
    }
}

// ---------------- W2_b[n][h*32+r] = sum_d Tmat_bh[d][r] * Wo[h*64+d][n] ----------------
__global__ __launch_bounds__(256)
void w2_kernel()
{
    int bh = blockIdx.x;            // b*16+h
    int h  = bh & 15;
    int b  = bh >> 4;
    int n  = blockIdx.y * 256 + threadIdx.x;   // output column 0..1023

    __shared__ float Tm[DH_][R_ + 1];
    for (int i = threadIdx.x; i < DH_ * R_; i += 256)
        Tm[i >> 5][i & 31] = g_Tmat[(size_t)bh * DH_ * R_ + i];
    __syncthreads();

    const __nv_bfloat16* wh = g_Woth + (size_t)n * D_ + h * DH_;
    const __nv_bfloat16* wl = g_Wotl + (size_t)n * D_ + h * DH_;

    float s[R_];
    #pragma unroll
    for (int r = 0; r < R_; r++) s[r] = 0.f;
    for (int d = 0; d < DH_; d++) {
        float w = __bfloat162float(wh[d]) + __bfloat162float(wl[d]);
        #pragma unroll
        for (int r = 0; r < R_; r++) s[r] += Tm[d][r] * w;
    }
    size_t base = ((size_t)b * 1024 + n) * ZK + h * R_;
    #pragma unroll
    for (int r = 0; r < R_; r++) {
        __nv_bfloat16 hv = __float2bfloat16(s[r]);
        g_W2h[base + r] = hv;
        g_W2l[base + r] = __float2bfloat16(s[r] - __bfloat162float(hv));
    }
}

// ---------------- launcher ----------------
extern "C" void kernel_launch(void* const* d_in, const int* in_sizes, int n_in,
                              void* d_out, int out_size)
{
    const float* hs     = (const float*)d_in[0];
    const float* Wk     = (const float*)d_in[1];
    const float* Wq     = (const float*)d_in[2];
    const float* Wv     = (const float*)d_in[3];
    const float* Wo     = (const float*)d_in[4];
    const float* lns    = (const float*)d_in[5];
    const float* lnb    = (const float*)d_in[6];
    const float* gate   = (const float*)d_in[7];
    const float* lridge = (const float*)d_in[8];
    const float* lgamma = (const float*)d_in[9];
    const int*   pl     = (const int*)d_in[10];
    float* out = (float*)d_out;

    cudaFuncSetAttribute(mma_gemm_kernel,
                         cudaFuncAttributeMaxDynamicSharedMemorySize, GEMM_SMEM);

    ln_split_kernel<<<MROWS, 256>>>(hs, lns, lnb);

    trans_split_kernel<<<dim3(16, 32), 256>>>(Wk, 512, 0, 0);
    trans_split_kernel<<<dim3(16, 32), 256>>>(Wq, 512, 0, 512 * 1024);
    trans_split_kernel<<<dim3(32, 32), 256>>>(Wv, 1024, 0, 1024 * 1024);
    trans_split_kernel<<<dim3(32, 32), 256>>>(Wo, 1024, 1, 0);

    mma_gemm_kernel<<<dim3(2048 / BN, MROWS / BM), 256, GEMM_SMEM>>>(nullptr, nullptr, pl, 0);

    build_partial_kernel<<<dim3(BH_, NCH), 256>>>(pl);
    solve_kernel<<<BH_, 256>>>(lridge, lgamma);
    w2_kernel<<<dim3(BH_, 4), 256>>>();

    mma_gemm_kernel<<<dim3(1024 / BN, MROWS / BM), 256, GEMM_SMEM>>>(out, gate, pl, 1);
}

// round 7
// speedup vs baseline: 6.7984x; 1.0159x over previous
#include <cuda_runtime.h>
#include <cuda_bf16.h>
#include <math.h>
#include <stdint.h>

#define B_    4
#define T_    4096
#define D_    1024
#define H_    16
#define R_    32
#define DH_   64
#define BH_   64
#define MROWS 16384
#define NCH   16
#define ZK    512              // Z feature dim (H_*R_)

// ---- mma.sync GEMM tiling ----
#define BM 128
#define BN 128
#define BK 32
#define ST_A_H 0
#define ST_A_L (8*1024)
#define ST_B_H (16*1024)
#define ST_B_L (24*1024)
#define STAGE  (32*1024)
#define NSTAGE 3
#define GEMM_SMEM (NSTAGE*STAGE)

// ---------------- scratch (device globals; no allocation) ----------------
__device__ __align__(128) __nv_bfloat16 g_Ah[(size_t)MROWS * D_];
__device__ __align__(128) __nv_bfloat16 g_Al[(size_t)MROWS * D_];
__device__ __align__(128) __nv_bfloat16 g_Wth[(size_t)2048 * D_];   // [n][k] KQV
__device__ __align__(128) __nv_bfloat16 g_Wtl[(size_t)2048 * D_];
__device__ __align__(128) __nv_bfloat16 g_Woth[(size_t)1024 * D_];  // [n][k] Wo
__device__ __align__(128) __nv_bfloat16 g_Wotl[(size_t)1024 * D_];
__device__ __align__(128) __nv_bfloat16 g_Zh[(size_t)MROWS * ZK];   // token z, hi
__device__ __align__(128) __nv_bfloat16 g_Zl[(size_t)MROWS * ZK];   // token z, lo
__device__ __align__(128) __nv_bfloat16 g_W2h[(size_t)B_ * 1024 * ZK]; // [b][n][k]
__device__ __align__(128) __nv_bfloat16 g_W2l[(size_t)B_ * 1024 * ZK];
__device__ float g_K[(size_t)BH_ * T_ * R_];
__device__ float g_V[(size_t)BH_ * T_ * DH_];
__device__ float g_part[(size_t)BH_ * NCH * 4096];
__device__ float g_Tmat[(size_t)BH_ * DH_ * R_];

// ---------------- PTX helpers (baseline ISA only) ----------------
__device__ __forceinline__ uint32_t smem_u32(const void* p) {
    uint32_t a;
    asm("{ .reg .u64 t; cvta.to.shared.u64 t, %1; cvt.u32.u64 %0, t; }" : "=r"(a) : "l"(p));
    return a;
}
__device__ __forceinline__ void cp16(uint32_t dst, const void* src) {
    asm volatile("cp.async.cg.shared.global [%0], [%1], 16;" :: "r"(dst), "l"(src) : "memory");
}
__device__ __forceinline__ void cp_commit() {
    asm volatile("cp.async.commit_group;" ::: "memory");
}
template<int N> __device__ __forceinline__ void cp_wait() {
    asm volatile("cp.async.wait_group %0;" :: "n"(N) : "memory");
}
__device__ __forceinline__ void ldsm4(uint32_t* r, uint32_t addr) {
    asm volatile("ldmatrix.sync.aligned.m8n8.x4.shared.b16 {%0,%1,%2,%3}, [%4];"
                 : "=r"(r[0]), "=r"(r[1]), "=r"(r[2]), "=r"(r[3]) : "r"(addr));
}
__device__ __forceinline__ void mma16816(float* c, const uint32_t* a, const uint32_t* b) {
    asm volatile("mma.sync.aligned.m16n8k16.row.col.f32.bf16.bf16.f32 "
                 "{%0,%1,%2,%3}, {%4,%5,%6,%7}, {%8,%9}, {%0,%1,%2,%3};"
                 : "+f"(c[0]), "+f"(c[1]), "+f"(c[2]), "+f"(c[3])
                 : "r"(a[0]), "r"(a[1]), "r"(a[2]), "r"(a[3]), "r"(b[0]), "r"(b[1]));
}
// 64B-row swizzle
__device__ __forceinline__ uint32_t swz64(uint32_t b) { return b ^ ((b >> 3) & 0x30); }

// ---------------- LayerNorm -> bf16 hi/lo ----------------
__global__ __launch_bounds__(256)
void ln_split_kernel(const float* __restrict__ x, const float* __restrict__ sc,
                     const float* __restrict__ bi)
{
    int row = blockIdx.x;
    int tid = threadIdx.x;
    const float4* xr = (const float4*)(x + (size_t)row * D_);
    float4 v = xr[tid];
    float s  = v.x + v.y + v.z + v.w;
    float ss = v.x*v.x + v.y*v.y + v.z*v.z + v.w*v.w;
    __shared__ float rs[8], rss[8];
    #pragma unroll
    for (int o = 16; o > 0; o >>= 1) {
        s  += __shfl_down_sync(0xffffffffu, s,  o);
        ss += __shfl_down_sync(0xffffffffu, ss, o);
    }
    int w = tid >> 5, l = tid & 31;
    if (l == 0) { rs[w] = s; rss[w] = ss; }
    __syncthreads();
    if (tid == 0) {
        float a = 0.f, b = 0.f;
        #pragma unroll
        for (int i = 0; i < 8; i++) { a += rs[i]; b += rss[i]; }
        rs[0] = a; rss[0] = b;
    }
    __syncthreads();
    float mu   = rs[0]  * (1.0f / D_);
    float var  = rss[0] * (1.0f / D_) - mu * mu;
    float rstd = rsqrtf(var + 1e-5f);
    float4 s4 = ((const float4*)sc)[tid];
    float4 b4 = ((const float4*)bi)[tid];
    float o0 = (v.x - mu) * rstd * s4.x + b4.x;
    float o1 = (v.y - mu) * rstd * s4.y + b4.y;
    float o2 = (v.z - mu) * rstd * s4.z + b4.z;
    float o3 = (v.w - mu) * rstd * s4.w + b4.w;
    size_t base = (size_t)row * D_ + tid * 4;
    __nv_bfloat16 h0 = __float2bfloat16(o0), h1 = __float2bfloat16(o1);
    __nv_bfloat16 h2 = __float2bfloat16(o2), h3 = __float2bfloat16(o3);
    g_Ah[base+0] = h0; g_Ah[base+1] = h1; g_Ah[base+2] = h2; g_Ah[base+3] = h3;
    g_Al[base+0] = __float2bfloat16(o0 - __bfloat162float(h0));
    g_Al[base+1] = __float2bfloat16(o1 - __bfloat162float(h1));
    g_Al[base+2] = __float2bfloat16(o2 - __bfloat162float(h2));
    g_Al[base+3] = __float2bfloat16(o3 - __bfloat162float(h3));
}

// ---------------- weight transpose + split (all 4 weights, z-indexed) ----------------
__global__ __launch_bounds__(256)
void trans_split_kernel(const float* __restrict__ Wk, const float* __restrict__ Wq,
                        const float* __restrict__ Wv, const float* __restrict__ Wo)
{
    __shared__ float tile[32][33];
    int z = blockIdx.z;
    const float* W;
    __nv_bfloat16 *dh, *dl;
    int N;
    if (z == 0)      { W = Wk; N = 512;  dh = g_Wth;  dl = g_Wtl; }
    else if (z == 1) { W = Wq; N = 512;  dh = g_Wth + 512 * 1024;  dl = g_Wtl + 512 * 1024; }
    else if (z == 2) { W = Wv; N = 1024; dh = g_Wth + 1024 * 1024; dl = g_Wtl + 1024 * 1024; }
    else             { W = Wo; N = 1024; dh = g_Woth; dl = g_Wotl; }
    int n0 = blockIdx.x * 32, k0 = blockIdx.y * 32;
    if (n0 >= N) return;
    int lane = threadIdx.x & 31, wrp = threadIdx.x >> 5;
    for (int i = wrp; i < 32; i += 8)
        tile[i][lane] = W[(size_t)(k0 + i) * N + n0 + lane];
    __syncthreads();
    for (int i = wrp; i < 32; i += 8) {
        float v = tile[lane][i];
        __nv_bfloat16 h = __float2bfloat16(v);
        dh[(size_t)(n0 + i) * D_ + k0 + lane] = h;
        dl[(size_t)(n0 + i) * D_ + k0 + lane] = __float2bfloat16(v - __bfloat162float(h));
    }
}

// ---------------- split-bf16 mma.sync GEMM (templated on mode) ----------------
// MODE 0: A=g_Ah/Al [16384][1024], B=g_Wth/Wtl [2048][1024]
//         skips dead tiles (K & V for t>=P, Q for t<P); epilogue: g_K, g_V, Z
// MODE 1: A=g_Zh/Zl [16384][512],  B=g_W2h/W2l (per-batch), out = sigmoid(gate)*C
template<int MODE>
__global__ __launch_bounds__(256, 2)
void mma_gemm_kernel(float* __restrict__ Cout, const float* __restrict__ gate,
                     const int* __restrict__ pl)
{
    extern __shared__ __align__(1024) char sm[];
    uint32_t sbase = smem_u32(sm);

    const int tid  = threadIdx.x;
    const int lane = tid & 31;
    const int wid  = tid >> 5;
    const int wm   = wid & 3;        // m block (32 rows)
    const int wn   = wid >> 2;       // n block (64 cols)
    const int m0   = blockIdx.y * BM;
    const int ntb  = blockIdx.x * BN;

    int P = *pl; if (P < 1) P = 1; if (P > T_ - 1) P = T_ - 1;

    if (MODE == 0) {
        int t0 = m0 & (T_ - 1);             // BM=128 rows share one batch
        if (ntb < 512) {                    // K region: only t < P read
            if (t0 >= P) return;
        } else if (ntb < 1024) {            // Q region: only t >= P read
            if (t0 + BM - 1 < P) return;
        } else {                            // V region: only t < P read
            if (t0 >= P) return;
        }
    }

    const __nv_bfloat16* Agh;
    const __nv_bfloat16* Agl;
    const __nv_bfloat16* Bgh;
    const __nv_bfloat16* Bgl;
    constexpr int lda = (MODE == 0) ? D_ : ZK;
    constexpr int kch = lda / BK;
    if (MODE == 0) {
        Agh = g_Ah; Agl = g_Al; Bgh = g_Wth; Bgl = g_Wtl;
    } else {
        size_t boff = (size_t)(m0 >> 12) * 1024 * ZK;
        Agh = g_Zh; Agl = g_Zl; Bgh = g_W2h + boff; Bgl = g_W2l + boff;
    }

    float acc[2][8][4];
    #pragma unroll
    for (int i = 0; i < 2; i++)
        #pragma unroll
        for (int j = 0; j < 8; j++)
            #pragma unroll
            for (int k = 0; k < 4; k++) acc[i][j][k] = 0.f;

    const int a_r15 = lane & 15;
    const int a_hi  = lane >> 4;
    const int b_nr  = (lane & 7) | ((lane >> 1) & 8);
    const int b_hi  = (lane >> 3) & 1;

    // loader: 512 16B-units per tensor, 2 per thread
    #define LOAD_STAGE(stg, koff)                                              \
        do {                                                                   \
            _Pragma("unroll")                                                  \
            for (int i_ = 0; i_ < 2; i_++) {                                   \
                int idx_ = tid + i_ * 256;                                     \
                int row_ = idx_ >> 2, u_ = idx_ & 3;                           \
                uint32_t d_ = swz64(row_ * 64 + u_ * 16);                      \
                size_t ka_ = (size_t)(m0 + row_) * lda + (koff) + u_ * 8;      \
                size_t kb_ = (size_t)(ntb + row_) * lda + (koff) + u_ * 8;     \
                cp16((stg) + ST_A_H + d_, Agh + ka_);                          \
                cp16((stg) + ST_A_L + d_, Agl + ka_);                          \
                cp16((stg) + ST_B_H + d_, Bgh + kb_);                          \
                cp16((stg) + ST_B_L + d_, Bgl + kb_);                          \
            }                                                                  \
            cp_commit();                                                       \
        } while (0)

    LOAD_STAGE(sbase, 0);
    LOAD_STAGE(sbase + STAGE, BK);

    int snext = 2;                 // stage receiving prefetch (issued post-sync)
    int scur  = 0;                 // stage being consumed
    for (int c = 0; c < kch; c++) {
        if (c + 1 < kch) cp_wait<1>(); else cp_wait<0>();
        __syncthreads();           // all warps done reading stage snext's old data
        if (c + 2 < kch) LOAD_STAGE(sbase + snext * STAGE, (c + 2) * BK);

        uint32_t st = sbase + scur * STAGE;
        #pragma unroll
        for (int ks = 0; ks < 2; ks++) {
            uint32_t ah0[4], ah1[4], al0[4], al1[4];
            {
                int u = ks * 2 + a_hi;
                uint32_t off0 = swz64((wm * 32 + a_r15) * 64 + u * 16);
                uint32_t off1 = swz64((wm * 32 + 16 + a_r15) * 64 + u * 16);
                ldsm4(ah0, st + ST_A_H + off0);
                ldsm4(ah1, st + ST_A_H + off1);
                ldsm4(al0, st + ST_A_L + off0);
                ldsm4(al1, st + ST_A_L + off1);
            }
            #pragma unroll
            for (int half = 0; half < 2; half++) {
                uint32_t bh[4][2], bl[4][2];
                #pragma unroll
                for (int p = 0; p < 2; p++) {
                    int u = ks * 2 + b_hi;
                    uint32_t off = swz64((wn * 64 + half * 32 + p * 16 + b_nr) * 64 + u * 16);
                    uint32_t r[4];
                    ldsm4(r, st + ST_B_H + off);
                    bh[p*2][0] = r[0]; bh[p*2][1] = r[1];
                    bh[p*2+1][0] = r[2]; bh[p*2+1][1] = r[3];
                    ldsm4(r, st + ST_B_L + off);
                    bl[p*2][0] = r[0]; bl[p*2][1] = r[1];
                    bl[p*2+1][0] = r[2]; bl[p*2+1][1] = r[3];
                }
                #pragma unroll
                for (int f = 0; f < 4; f++) {
                    int nf = half * 4 + f;
                    mma16816(acc[0][nf], ah0, bh[f]);
                    mma16816(acc[1][nf], ah1, bh[f]);
                    mma16816(acc[0][nf], ah0, bl[f]);
                    mma16816(acc[1][nf], ah1, bl[f]);
                    mma16816(acc[0][nf], al0, bh[f]);
                    mma16816(acc[1][nf], al1, bh[f]);
                }
            }
        }
        scur  = (scur == NSTAGE - 1) ? 0 : scur + 1;
        snext = (snext == NSTAGE - 1) ? 0 : snext + 1;
    }

    // ---- epilogue ----
    float gm = (MODE == 1) ? (1.0f / (1.0f + expf(-gate[0]))) : 1.0f;
    #pragma unroll
    for (int mf = 0; mf < 2; mf++) {
        int mrow0 = m0 + wm * 32 + mf * 16 + (lane >> 2);
        #pragma unroll
        for (int nf = 0; nf < 8; nf++) {
            int n = ntb + wn * 64 + nf * 8 + (lane & 3) * 2;
            #pragma unroll
            for (int rh = 0; rh < 2; rh++) {
                int m = mrow0 + rh * 8;
                float2 v;
                v.x = gm * acc[mf][nf][rh * 2 + 0];
                v.y = gm * acc[mf][nf][rh * 2 + 1];
                if (MODE == 1) {
                    *(float2*)(Cout + (size_t)m * 1024 + n) = v;
                } else {
                    int b = m >> 12, t = m & (T_ - 1);
                    if (n < 1024) {
                        int zc = (n < 512) ? n : (n - 512);
                        bool emit = (n < 512) ? (t < P) : (t >= P);
                        if (emit) {
                            __nv_bfloat162 hv, lv;
                            hv.x = __float2bfloat16(v.x);
                            hv.y = __float2bfloat16(v.y);
                            lv.x = __float2bfloat16(v.x - __bfloat162float(hv.x));
                            lv.y = __float2bfloat16(v.y - __bfloat162float(hv.y));
                            *(__nv_bfloat162*)(g_Zh + (size_t)m * ZK + zc) = hv;
                            *(__nv_bfloat162*)(g_Zl + (size_t)m * ZK + zc) = lv;
                        }
                        if (n < 512) {
                            float* dst = g_K + (((size_t)(b * H_ + (n >> 5))) * T_ + t) * R_ + (n & 31);
                            *(float2*)dst = v;
                        }
                    } else {
                        int nv = n - 1024;
                        float* dst = g_V + (((size_t)(b * H_ + (nv >> 6))) * T_ + t) * DH_ + (nv & 63);
                        *(float2*)dst = v;
                    }
                }
            }
        }
    }
}

// ---------------- partial G/M/Cv accumulation ----------------
__global__ __launch_bounds__(256)
void build_partial_kernel(const int* __restrict__ pl)
{
    int bh = blockIdx.x;
    int chunk = blockIdx.y;
    int P = *pl; if (P < 1) P = 1; if (P > T_ - 1) P = T_ - 1;
    int ch = (P + NCH - 1) / NCH;
    int lo = chunk * ch;
    int hi = min(lo + ch, P);

    const float* K = g_K + (size_t)bh * T_ * R_;
    const float* V = g_V + (size_t)bh * T_ * DH_;
    __shared__ __align__(16) float Ks[65][32];
    __shared__ __align__(16) float Vs[64][64];

    int tid = threadIdx.x;
    int r  = tid & 31, sg = tid >> 5;
    int d  = tid & 63, rg = tid >> 6;
    float gacc[4] = {0, 0, 0, 0};
    float macc[4] = {0, 0, 0, 0};
    float cacc[8] = {0, 0, 0, 0, 0, 0, 0, 0};

    for (int t0 = lo; t0 < hi; t0 += 64) {
        int nrows = min(64, hi - t0);
        for (int idx = tid; idx < (nrows + 1) * 8; idx += 256) {
            int rr = idx >> 3, cq = (idx & 7) * 4;
            *(float4*)&Ks[rr][cq] = *(const float4*)&K[(size_t)(t0 + rr) * R_ + cq];
        }
        for (int idx = tid; idx < nrows * 16; idx += 256) {
            int rr = idx >> 4, cq = (idx & 15) * 4;
            *(float4*)&Vs[rr][cq] = *(const float4*)&V[(size_t)(t0 + rr) * DH_ + cq];
        }
        __syncthreads();
        for (int tt = 0; tt < nrows; tt++) {
            int t = t0 + tt;
            float kr  = Ks[tt][r];
            float ks0 = Ks[tt][sg * 4 + 0], ks1 = Ks[tt][sg * 4 + 1];
            float ks2 = Ks[tt][sg * 4 + 2], ks3 = Ks[tt][sg * 4 + 3];
            gacc[0] += kr * ks0; gacc[1] += kr * ks1;
            gacc[2] += kr * ks2; gacc[3] += kr * ks3;
            if (t < P - 1) {
                float kn = Ks[tt + 1][r];
                macc[0] += kn * ks0; macc[1] += kn * ks1;
                macc[2] += kn * ks2; macc[3] += kn * ks3;
            }
            float vv = Vs[tt][d];
            #pragma unroll
            for (int j = 0; j < 8; j++) cacc[j] += vv * Ks[tt][rg * 8 + j];
        }
        __syncthreads();
    }
    float* out = g_part + ((size_t)bh * NCH + chunk) * 4096;
    #pragma unroll
    for (int j = 0; j < 4; j++) {
        out[r * 32 + sg * 4 + j]        = gacc[j];
        out[1024 + r * 32 + sg * 4 + j] = macc[j];
    }
    #pragma unroll
    for (int j = 0; j < 8; j++) out[2048 + d * 32 + rg * 8 + j] = cacc[j];
}

// ---------------- per-head solve ----------------
#define MM32(Cm, Am, Bm)                                                     \
    do {                                                                     \
        for (int e = tid; e < 1024; e += 256) {                              \
            int rr = e >> 5, cc = e & 31; float s = 0.f;                     \
            _Pragma("unroll") for (int k2 = 0; k2 < 32; k2++)                \
                s += Am[rr][k2] * Bm[k2][cc];                                \
            Cm[rr][cc] = s;                                                  \
        }                                                                    \
        __syncthreads();                                                     \
    } while (0)

__global__ __launch_bounds__(256)
void solve_kernel(const float* __restrict__ lridge, const float* __restrict__ lgamma)
{
    __shared__ float sG[32][33], sM[32][33], sL[32][33], sLi[32][33];
    __shared__ float sAw[32][33], sT[32][33];
    __shared__ float sCv[64][33], sBv[64][33];
    __shared__ float sScale;

    int bh = blockIdx.x;
    int tid = threadIdx.x;

    const float* base = g_part + (size_t)bh * NCH * 4096;
    for (int idx = tid; idx < 4096; idx += 256) {
        float s = 0.f;
        #pragma unroll
        for (int c = 0; c < NCH; c++) s += base[(size_t)c * 4096 + idx];
        if (idx < 1024)      sG[idx >> 5][idx & 31] = s;
        else if (idx < 2048) sM[(idx - 1024) >> 5][idx & 31] = s;
        else { int e = idx - 2048; sCv[e >> 5][e & 31] = s; }
    }
    __syncthreads();
    if (tid < 32) sG[tid][tid] += expf(lridge[0]);
    __syncthreads();

    if (tid < 32) {
        int i = tid;
        for (int j = 0; j < 32; j++) {
            if (i == j) {
                float s = sG[j][j];
                for (int k = 0; k < j; k++) s -= sL[j][k] * sL[j][k];
                sL[j][j] = sqrtf(fmaxf(s, 1e-30f));
            }
            __syncwarp();
            if (i > j) {
                float s = sG[i][j];
                for (int k = 0; k < j; k++) s -= sL[i][k] * sL[j][k];
                sL[i][j] = s / sL[j][j];
            } else if (i < j) {
                sL[i][j] = 0.f;
            }
            __syncwarp();
        }
        int j = tid;
        for (int i2 = 0; i2 < 32; i2++) sLi[i2][j] = 0.f;
        for (int i2 = j; i2 < 32; i2++) {
            float s = (i2 == j) ? 1.f : 0.f;
            for (int k = j; k < i2; k++) s -= sL[i2][k] * sLi[k][j];
            sLi[i2][j] = s / sL[i2][i2];
        }
    }
    __syncthreads();

    MM32(sT, sLi, sM);
    for (int e = tid; e < 1024; e += 256) {
        int rr = e >> 5, cc = e & 31; float s = 0.f;
        #pragma unroll
        for (int k2 = 0; k2 < 32; k2++) s += sT[rr][k2] * sLi[cc][k2];
        sAw[rr][cc] = s;
    }
    __syncthreads();

    if (tid < 32) {
        int i = tid;
        float v = 1.0f + 0.37f * (float)i;
        float sig = 0.f;
        for (int it = 0; it < 200; it++) {
            float u = 0.f;
            #pragma unroll
            for (int k = 0; k < 32; k++) u += sAw[i][k] * __shfl_sync(0xffffffffu, v, k);
            float w = 0.f;
            #pragma unroll
            for (int k = 0; k < 32; k++) w += sAw[k][i] * __shfl_sync(0xffffffffu, u, k);
            float n2 = w * w;
            #pragma unroll
            for (int o = 16; o > 0; o >>= 1) n2 += __shfl_xor_sync(0xffffffffu, n2, o);
            float nrm = sqrtf(n2);
            v = w / fmaxf(nrm, 1e-30f);
            sig = sqrtf(nrm);
        }
        if (i == 0) {
            float gamma = expf(lgamma[0]);
            float gc = fminf(gamma, 1.0f);
            float s0 = fmaxf(sig, 1e-8f);
            sScale = gc / fmaxf(s0, 1.0f);
        }
    }
    __syncthreads();
    float scl = sScale;
    for (int e = tid; e < 1024; e += 256) sAw[e >> 5][e & 31] *= scl;
    __syncthreads();

    MM32(sT, sAw, sAw);
    MM32(sM, sT, sT);
    MM32(sG, sM, sLi);
    MM32(sT, sL, sG);

    for (int e = tid; e < 2048; e += 256) {
        int dd = e >> 5, rr = e & 31; float s = 0.f;
        #pragma unroll
        for (int k2 = 0; k2 < 32; k2++) s += sCv[dd][k2] * sLi[rr][k2];
        sBv[dd][rr] = s;
    }
    __syncthreads();
    for (int e = tid; e < 2048; e += 256) {
        int dd = e >> 5, rr = e & 31; float s = 0.f;
        #pragma unroll
        for (int k2 = 0; k2 < 32; k2++) s += sBv[dd][k2] * sLi[k2][rr];
        sCv[dd][rr] = s;
    }
    __syncthreads();

    float* tm = g_Tmat + (size_t)bh * DH_ * R_;
    for (int e = tid; e < 2048; e += 256) {
        int dd = e >> 5, rr = e & 31; float s = 0.f;
        #pragma unroll
        for (int k2 = 0; k2 < 32; k2++) s += sCv[dd][k2] * sT[k2][rr];
        tm[dd * R_ + rr] = s;
    }
}

// ---------------- W2_b[n][h*32+r] = sum_d Tmat_bh[d][r] * Wo[h*64+d][n] ----------------
__global__ __launch_bounds__(256)
void w2_kernel()
{
    int bh = blockIdx.x;            // b*16+h
    int h  = bh & 15;
    int b  = bh >> 4;
    int n  = blockIdx.y * 256 + threadIdx.x;   // output column 0..1023

    __shared__ float Tm[DH_][R_ + 1];
    for (int i = threadIdx.x; i < DH_ * R_; i += 256)
        Tm[i >> 5][i & 31] = g_Tmat[(size_t)bh * DH_ * R_ + i];
    __syncthreads();

    const __nv_bfloat16* wh = g_Woth + (size_t)n * D_ + h * DH_;
    const __nv_bfloat16* wl = g_Wotl + (size_t)n * D_ + h * DH_;

    float s[R_];
    #pragma unroll
    for (int r = 0; r < R_; r++) s[r] = 0.f;
    for (int d = 0; d < DH_; d++) {
        float w = __bfloat162float(wh[d]) + __bfloat162float(wl[d]);
        #pragma unroll
        for (int r = 0; r < R_; r++) s[r] += Tm[d][r] * w;
    }
    size_t base = ((size_t)b * 1024 + n) * ZK + h * R_;
    #pragma unroll
    for (int r = 0; r < R_; r++) {
        __nv_bfloat16 hv = __float2bfloat16(s[r]);
        g_W2h[base + r] = hv;
        g_W2l[base + r] = __float2bfloat16(s[r] - __bfloat162float(hv));
    }
}

// ---------------- launcher ----------------
extern "C" void kernel_launch(void* const* d_in, const int* in_sizes, int n_in,
                              void* d_out, int out_size)
{
    const float* hs     = (const float*)d_in[0];
    const float* Wk     = (const float*)d_in[1];
    const float* Wq     = (const float*)d_in[2];
    const float* Wv     = (const float*)d_in[3];
    const float* Wo     = (const float*)d_in[4];
    const float* lns    = (const float*)d_in[5];
    const float* lnb    = (const float*)d_in[6];
    const float* gate   = (const float*)d_in[7];
    const float* lridge = (const float*)d_in[8];
    const float* lgamma = (const float*)d_in[9];
    const int*   pl     = (const int*)d_in[10];
    float* out = (float*)d_out;

    cudaFuncSetAttribute(mma_gemm_kernel<0>,
                         cudaFuncAttributeMaxDynamicSharedMemorySize, GEMM_SMEM);
    cudaFuncSetAttribute(mma_gemm_kernel<1>,
                         cudaFuncAttributeMaxDynamicSharedMemorySize, GEMM_SMEM);

    ln_split_kernel<<<MROWS, 256>>>(hs, lns, lnb);

    trans_split_kernel<<<dim3(32, 32, 4), 256>>>(Wk, Wq, Wv, Wo);

    mma_gemm_kernel<0><<<dim3(2048 / BN, MROWS / BM), 256, GEMM_SMEM>>>(nullptr, nullptr, pl);

    build_partial_kernel<<<dim3(BH_, NCH), 256>>>(pl);
    solve_kernel<<<BH_, 256>>>(lridge, lgamma);
    w2_kernel<<<dim3(BH_, 4), 256>>>();

    mma_gemm_kernel<1><<<dim3(1024 / BN, MROWS / BM), 256, GEMM_SMEM>>>(out, gate, pl);
}

// round 8
// speedup vs baseline: 7.5518x; 1.1108x over previous
#include <cuda_runtime.h>
#include <cuda_bf16.h>
#include <math.h>
#include <stdint.h>

#define B_    4
#define T_    4096
#define D_    1024
#define H_    16
#define R_    32
#define DH_   64
#define BH_   64
#define MROWS 16384
#define NCH   16
#define ZK    512              // Z feature dim (H_*R_)

// ---- mma.sync GEMM tiling ----
#define BM 128
#define BN 128
#define BK 32
#define ST_A_H 0
#define ST_A_L (8*1024)
#define ST_B_H (16*1024)
#define ST_B_L (24*1024)
#define STAGE  (32*1024)
#define NSTAGE 3
#define GEMM_SMEM (NSTAGE*STAGE)

// ---------------- scratch (device globals; no allocation) ----------------
__device__ __align__(128) __nv_bfloat16 g_Ah[(size_t)MROWS * D_];
__device__ __align__(128) __nv_bfloat16 g_Al[(size_t)MROWS * D_];
__device__ __align__(128) __nv_bfloat16 g_Wth[(size_t)2048 * D_];   // [n][k] KQV
__device__ __align__(128) __nv_bfloat16 g_Wtl[(size_t)2048 * D_];
__device__ __align__(128) __nv_bfloat16 g_Woth[(size_t)1024 * D_];  // [n][k] Wo
__device__ __align__(128) __nv_bfloat16 g_Wotl[(size_t)1024 * D_];
__device__ __align__(128) __nv_bfloat16 g_Zh[(size_t)MROWS * ZK];   // token z, hi
__device__ __align__(128) __nv_bfloat16 g_Zl[(size_t)MROWS * ZK];   // token z, lo
__device__ __align__(128) __nv_bfloat16 g_W2h[(size_t)B_ * 1024 * ZK]; // [b][n][k]
__device__ __align__(128) __nv_bfloat16 g_W2l[(size_t)B_ * 1024 * ZK];
__device__ float g_K[(size_t)BH_ * T_ * R_];
__device__ float g_V[(size_t)BH_ * T_ * DH_];
__device__ float g_part[(size_t)BH_ * NCH * 4096];
__device__ float g_Tmat[(size_t)BH_ * DH_ * R_];

// ---------------- PTX helpers (baseline ISA only) ----------------
__device__ __forceinline__ uint32_t smem_u32(const void* p) {
    uint32_t a;
    asm("{ .reg .u64 t; cvta.to.shared.u64 t, %1; cvt.u32.u64 %0, t; }" : "=r"(a) : "l"(p));
    return a;
}
__device__ __forceinline__ void cp16(uint32_t dst, const void* src) {
    asm volatile("cp.async.cg.shared.global [%0], [%1], 16;" :: "r"(dst), "l"(src) : "memory");
}
__device__ __forceinline__ void cp_commit() {
    asm volatile("cp.async.commit_group;" ::: "memory");
}
template<int N> __device__ __forceinline__ void cp_wait() {
    asm volatile("cp.async.wait_group %0;" :: "n"(N) : "memory");
}
__device__ __forceinline__ void ldsm4(uint32_t* r, uint32_t addr) {
    asm volatile("ldmatrix.sync.aligned.m8n8.x4.shared.b16 {%0,%1,%2,%3}, [%4];"
                 : "=r"(r[0]), "=r"(r[1]), "=r"(r[2]), "=r"(r[3]) : "r"(addr));
}
__device__ __forceinline__ void mma16816(float* c, const uint32_t* a, const uint32_t* b) {
    asm volatile("mma.sync.aligned.m16n8k16.row.col.f32.bf16.bf16.f32 "
                 "{%0,%1,%2,%3}, {%4,%5,%6,%7}, {%8,%9}, {%0,%1,%2,%3};"
                 : "+f"(c[0]), "+f"(c[1]), "+f"(c[2]), "+f"(c[3])
                 : "r"(a[0]), "r"(a[1]), "r"(a[2]), "r"(a[3]), "r"(b[0]), "r"(b[1]));
}
// 64B-row swizzle
__device__ __forceinline__ uint32_t swz64(uint32_t b) { return b ^ ((b >> 3) & 0x30); }

// ---------------- LayerNorm -> bf16 hi/lo ----------------
__global__ __launch_bounds__(256)
void ln_split_kernel(const float* __restrict__ x, const float* __restrict__ sc,
                     const float* __restrict__ bi)
{
    int row = blockIdx.x;
    int tid = threadIdx.x;
    const float4* xr = (const float4*)(x + (size_t)row * D_);
    float4 v = xr[tid];
    float s  = v.x + v.y + v.z + v.w;
    float ss = v.x*v.x + v.y*v.y + v.z*v.z + v.w*v.w;
    __shared__ float rs[8], rss[8];
    #pragma unroll
    for (int o = 16; o > 0; o >>= 1) {
        s  += __shfl_down_sync(0xffffffffu, s,  o);
        ss += __shfl_down_sync(0xffffffffu, ss, o);
    }
    int w = tid >> 5, l = tid & 31;
    if (l == 0) { rs[w] = s; rss[w] = ss; }
    __syncthreads();
    if (tid == 0) {
        float a = 0.f, b = 0.f;
        #pragma unroll
        for (int i = 0; i < 8; i++) { a += rs[i]; b += rss[i]; }
        rs[0] = a; rss[0] = b;
    }
    __syncthreads();
    float mu   = rs[0]  * (1.0f / D_);
    float var  = rss[0] * (1.0f / D_) - mu * mu;
    float rstd = rsqrtf(var + 1e-5f);
    float4 s4 = ((const float4*)sc)[tid];
    float4 b4 = ((const float4*)bi)[tid];
    float o0 = (v.x - mu) * rstd * s4.x + b4.x;
    float o1 = (v.y - mu) * rstd * s4.y + b4.y;
    float o2 = (v.z - mu) * rstd * s4.z + b4.z;
    float o3 = (v.w - mu) * rstd * s4.w + b4.w;
    size_t base = (size_t)row * D_ + tid * 4;
    __nv_bfloat16 h0 = __float2bfloat16(o0), h1 = __float2bfloat16(o1);
    __nv_bfloat16 h2 = __float2bfloat16(o2), h3 = __float2bfloat16(o3);
    g_Ah[base+0] = h0; g_Ah[base+1] = h1; g_Ah[base+2] = h2; g_Ah[base+3] = h3;
    g_Al[base+0] = __float2bfloat16(o0 - __bfloat162float(h0));
    g_Al[base+1] = __float2bfloat16(o1 - __bfloat162float(h1));
    g_Al[base+2] = __float2bfloat16(o2 - __bfloat162float(h2));
    g_Al[base+3] = __float2bfloat16(o3 - __bfloat162float(h3));
}

// ---------------- weight transpose + split (all 4 weights, z-indexed) ----------------
__global__ __launch_bounds__(256)
void trans_split_kernel(const float* __restrict__ Wk, const float* __restrict__ Wq,
                        const float* __restrict__ Wv, const float* __restrict__ Wo)
{
    __shared__ float tile[32][33];
    int z = blockIdx.z;
    const float* W;
    __nv_bfloat16 *dh, *dl;
    int N;
    if (z == 0)      { W = Wk; N = 512;  dh = g_Wth;  dl = g_Wtl; }
    else if (z == 1) { W = Wq; N = 512;  dh = g_Wth + 512 * 1024;  dl = g_Wtl + 512 * 1024; }
    else if (z == 2) { W = Wv; N = 1024; dh = g_Wth + 1024 * 1024; dl = g_Wtl + 1024 * 1024; }
    else             { W = Wo; N = 1024; dh = g_Woth; dl = g_Wotl; }
    int n0 = blockIdx.x * 32, k0 = blockIdx.y * 32;
    if (n0 >= N) return;
    int lane = threadIdx.x & 31, wrp = threadIdx.x >> 5;
    for (int i = wrp; i < 32; i += 8)
        tile[i][lane] = W[(size_t)(k0 + i) * N + n0 + lane];
    __syncthreads();
    for (int i = wrp; i < 32; i += 8) {
        float v = tile[lane][i];
        __nv_bfloat16 h = __float2bfloat16(v);
        dh[(size_t)(n0 + i) * D_ + k0 + lane] = h;
        dl[(size_t)(n0 + i) * D_ + k0 + lane] = __float2bfloat16(v - __bfloat162float(h));
    }
}

// ---------------- split-bf16 mma.sync GEMM (templated on mode) ----------------
// MODE 0: A=g_Ah/Al [16384][1024], B=g_Wth/Wtl [2048][1024]
//         skips dead tiles (K & V for t>=P, Q for t<P); epilogue: g_K, g_V, Z
// MODE 1: A=g_Zh/Zl [16384][512],  B=g_W2h/W2l (per-batch), out = sigmoid(gate)*C
template<int MODE>
__global__ __launch_bounds__(256, 2)
void mma_gemm_kernel(float* __restrict__ Cout, const float* __restrict__ gate,
                     const int* __restrict__ pl)
{
    extern __shared__ __align__(1024) char sm[];
    uint32_t sbase = smem_u32(sm);

    const int tid  = threadIdx.x;
    const int lane = tid & 31;
    const int wid  = tid >> 5;
    const int wm   = wid & 3;        // m block (32 rows)
    const int wn   = wid >> 2;       // n block (64 cols)
    const int m0   = blockIdx.y * BM;
    const int ntb  = blockIdx.x * BN;

    int P = *pl; if (P < 1) P = 1; if (P > T_ - 1) P = T_ - 1;

    if (MODE == 0) {
        int t0 = m0 & (T_ - 1);             // BM=128 rows share one batch
        if (ntb < 512) {                    // K region: only t < P read
            if (t0 >= P) return;
        } else if (ntb < 1024) {            // Q region: only t >= P read
            if (t0 + BM - 1 < P) return;
        } else {                            // V region: only t < P read
            if (t0 >= P) return;
        }
    }

    const __nv_bfloat16* Agh;
    const __nv_bfloat16* Agl;
    const __nv_bfloat16* Bgh;
    const __nv_bfloat16* Bgl;
    constexpr int lda = (MODE == 0) ? D_ : ZK;
    constexpr int kch = lda / BK;
    if (MODE == 0) {
        Agh = g_Ah; Agl = g_Al; Bgh = g_Wth; Bgl = g_Wtl;
    } else {
        size_t boff = (size_t)(m0 >> 12) * 1024 * ZK;
        Agh = g_Zh; Agl = g_Zl; Bgh = g_W2h + boff; Bgl = g_W2l + boff;
    }

    float acc[2][8][4];
    #pragma unroll
    for (int i = 0; i < 2; i++)
        #pragma unroll
        for (int j = 0; j < 8; j++)
            #pragma unroll
            for (int k = 0; k < 4; k++) acc[i][j][k] = 0.f;

    const int a_r15 = lane & 15;
    const int a_hi  = lane >> 4;
    const int b_nr  = (lane & 7) | ((lane >> 1) & 8);
    const int b_hi  = (lane >> 3) & 1;

    // loader: 512 16B-units per tensor, 2 per thread
    #define LOAD_STAGE(stg, koff)                                              \
        do {                                                                   \
            _Pragma("unroll")                                                  \
            for (int i_ = 0; i_ < 2; i_++) {                                   \
                int idx_ = tid + i_ * 256;                                     \
                int row_ = idx_ >> 2, u_ = idx_ & 3;                           \
                uint32_t d_ = swz64(row_ * 64 + u_ * 16);                      \
                size_t ka_ = (size_t)(m0 + row_) * lda + (koff) + u_ * 8;      \
                size_t kb_ = (size_t)(ntb + row_) * lda + (koff) + u_ * 8;     \
                cp16((stg) + ST_A_H + d_, Agh + ka_);                          \
                cp16((stg) + ST_A_L + d_, Agl + ka_);                          \
                cp16((stg) + ST_B_H + d_, Bgh + kb_);                          \
                cp16((stg) + ST_B_L + d_, Bgl + kb_);                          \
            }                                                                  \
            cp_commit();                                                       \
        } while (0)

    LOAD_STAGE(sbase, 0);
    LOAD_STAGE(sbase + STAGE, BK);

    int snext = 2;                 // stage receiving prefetch (issued post-sync)
    int scur  = 0;                 // stage being consumed
    for (int c = 0; c < kch; c++) {
        if (c + 1 < kch) cp_wait<1>(); else cp_wait<0>();
        __syncthreads();           // all warps done reading stage snext's old data
        if (c + 2 < kch) LOAD_STAGE(sbase + snext * STAGE, (c + 2) * BK);

        uint32_t st = sbase + scur * STAGE;
        #pragma unroll
        for (int ks = 0; ks < 2; ks++) {
            uint32_t ah0[4], ah1[4], al0[4], al1[4];
            {
                int u = ks * 2 + a_hi;
                uint32_t off0 = swz64((wm * 32 + a_r15) * 64 + u * 16);
                uint32_t off1 = swz64((wm * 32 + 16 + a_r15) * 64 + u * 16);
                ldsm4(ah0, st + ST_A_H + off0);
                ldsm4(ah1, st + ST_A_H + off1);
                ldsm4(al0, st + ST_A_L + off0);
                ldsm4(al1, st + ST_A_L + off1);
            }
            #pragma unroll
            for (int half = 0; half < 2; half++) {
                uint32_t bh[4][2], bl[4][2];
                #pragma unroll
                for (int p = 0; p < 2; p++) {
                    int u = ks * 2 + b_hi;
                    uint32_t off = swz64((wn * 64 + half * 32 + p * 16 + b_nr) * 64 + u * 16);
                    uint32_t r[4];
                    ldsm4(r, st + ST_B_H + off);
                    bh[p*2][0] = r[0]; bh[p*2][1] = r[1];
                    bh[p*2+1][0] = r[2]; bh[p*2+1][1] = r[3];
                    ldsm4(r, st + ST_B_L + off);
                    bl[p*2][0] = r[0]; bl[p*2][1] = r[1];
                    bl[p*2+1][0] = r[2]; bl[p*2+1][1] = r[3];
                }
                #pragma unroll
                for (int f = 0; f < 4; f++) {
                    int nf = half * 4 + f;
                    mma16816(acc[0][nf], ah0, bh[f]);
                    mma16816(acc[1][nf], ah1, bh[f]);
                    mma16816(acc[0][nf], ah0, bl[f]);
                    mma16816(acc[1][nf], ah1, bl[f]);
                    mma16816(acc[0][nf], al0, bh[f]);
                    mma16816(acc[1][nf], al1, bh[f]);
                }
            }
        }
        scur  = (scur == NSTAGE - 1) ? 0 : scur + 1;
        snext = (snext == NSTAGE - 1) ? 0 : snext + 1;
    }

    // ---- epilogue ----
    float gm = (MODE == 1) ? (1.0f / (1.0f + expf(-gate[0]))) : 1.0f;
    #pragma unroll
    for (int mf = 0; mf < 2; mf++) {
        int mrow0 = m0 + wm * 32 + mf * 16 + (lane >> 2);
        #pragma unroll
        for (int nf = 0; nf < 8; nf++) {
            int n = ntb + wn * 64 + nf * 8 + (lane & 3) * 2;
            #pragma unroll
            for (int rh = 0; rh < 2; rh++) {
                int m = mrow0 + rh * 8;
                float2 v;
                v.x = gm * acc[mf][nf][rh * 2 + 0];
                v.y = gm * acc[mf][nf][rh * 2 + 1];
                if (MODE == 1) {
                    *(float2*)(Cout + (size_t)m * 1024 + n) = v;
                } else {
                    int b = m >> 12, t = m & (T_ - 1);
                    if (n < 1024) {
                        int zc = (n < 512) ? n : (n - 512);
                        bool emit = (n < 512) ? (t < P) : (t >= P);
                        if (emit) {
                            __nv_bfloat162 hv, lv;
                            hv.x = __float2bfloat16(v.x);
                            hv.y = __float2bfloat16(v.y);
                            lv.x = __float2bfloat16(v.x - __bfloat162float(hv.x));
                            lv.y = __float2bfloat16(v.y - __bfloat162float(hv.y));
                            *(__nv_bfloat162*)(g_Zh + (size_t)m * ZK + zc) = hv;
                            *(__nv_bfloat162*)(g_Zl + (size_t)m * ZK + zc) = lv;
                        }
                        if (n < 512) {
                            float* dst = g_K + (((size_t)(b * H_ + (n >> 5))) * T_ + t) * R_ + (n & 31);
                            *(float2*)dst = v;
                        }
                    } else {
                        int nv = n - 1024;
                        float* dst = g_V + (((size_t)(b * H_ + (nv >> 6))) * T_ + t) * DH_ + (nv & 63);
                        *(float2*)dst = v;
                    }
                }
            }
        }
    }
}

// ---------------- partial G/M/Cv accumulation (vectorized) ----------------
// thread: r = tid&31; g = tid>>5 selects BOTH the s-block (G/M: s=g*4..+3)
// and the d-block (Cv: d=g*8..+7). Per t: 2 scalar LDS + 3 float4 broadcast
// LDS + 16 FMA. kr is reused by G and Cv.
__global__ __launch_bounds__(256)
void build_partial_kernel(const int* __restrict__ pl)
{
    int bh = blockIdx.x;
    int chunk = blockIdx.y;
    int P = *pl; if (P < 1) P = 1; if (P > T_ - 1) P = T_ - 1;
    int ch = (P + NCH - 1) / NCH;
    int lo = chunk * ch;
    int hi = min(lo + ch, P);
    int Pm1 = P - 1;

    const float* K = g_K + (size_t)bh * T_ * R_;
    const float* V = g_V + (size_t)bh * T_ * DH_;
    __shared__ __align__(16) float Ks[65][32];
    __shared__ __align__(16) float Vs[64][64];

    int tid = threadIdx.x;
    int r = tid & 31, g = tid >> 5;
    float4 gacc = {0, 0, 0, 0};
    float4 macc = {0, 0, 0, 0};
    float4 ca   = {0, 0, 0, 0};
    float4 cb   = {0, 0, 0, 0};

    for (int t0 = lo; t0 < hi; t0 += 64) {
        int nrows = min(64, hi - t0);
        for (int idx = tid; idx < (nrows + 1) * 8; idx += 256) {
            int rr = idx >> 3, cq = (idx & 7) * 4;
            *(float4*)&Ks[rr][cq] = *(const float4*)&K[(size_t)(t0 + rr) * R_ + cq];
        }
        for (int idx = tid; idx < nrows * 16; idx += 256) {
            int rr = idx >> 4, cq = (idx & 15) * 4;
            *(float4*)&Vs[rr][cq] = *(const float4*)&V[(size_t)(t0 + rr) * DH_ + cq];
        }
        __syncthreads();
        #pragma unroll 4
        for (int tt = 0; tt < nrows; tt++) {
            float kr = Ks[tt][r];
            float kn = (t0 + tt < Pm1) ? Ks[tt + 1][r] : 0.f;
            float4 ks = *(const float4*)&Ks[tt][g * 4];
            float4 va = *(const float4*)&Vs[tt][g * 8];
            float4 vb = *(const float4*)&Vs[tt][g * 8 + 4];
            gacc.x += kr * ks.x; gacc.y += kr * ks.y;
            gacc.z += kr * ks.z; gacc.w += kr * ks.w;
            macc.x += kn * ks.x; macc.y += kn * ks.y;
            macc.z += kn * ks.z; macc.w += kn * ks.w;
            ca.x += kr * va.x; ca.y += kr * va.y;
            ca.z += kr * va.z; ca.w += kr * va.w;
            cb.x += kr * vb.x; cb.y += kr * vb.y;
            cb.z += kr * vb.z; cb.w += kr * vb.w;
        }
        __syncthreads();
    }
    float* out = g_part + ((size_t)bh * NCH + chunk) * 4096;
    // G[r][s], M[r][s] for s = g*4..+3
    out[r * 32 + g * 4 + 0] = gacc.x;  out[r * 32 + g * 4 + 1] = gacc.y;
    out[r * 32 + g * 4 + 2] = gacc.z;  out[r * 32 + g * 4 + 3] = gacc.w;
    out[1024 + r * 32 + g * 4 + 0] = macc.x;  out[1024 + r * 32 + g * 4 + 1] = macc.y;
    out[1024 + r * 32 + g * 4 + 2] = macc.z;  out[1024 + r * 32 + g * 4 + 3] = macc.w;
    // Cv[d][r] for d = g*8..+7
    #pragma unroll
    for (int j = 0; j < 4; j++) {
        out[2048 + (g * 8 + j) * 32 + r]     = (&ca.x)[j];
        out[2048 + (g * 8 + 4 + j) * 32 + r] = (&cb.x)[j];
    }
}

// ---------------- per-head solve ----------------
#define MM32(Cm, Am, Bm)                                                     \
    do {                                                                     \
        for (int e = tid; e < 1024; e += 256) {                              \
            int rr = e >> 5, cc = e & 31; float s = 0.f;                     \
            _Pragma("unroll") for (int k2 = 0; k2 < 32; k2++)                \
                s += Am[rr][k2] * Bm[k2][cc];                                \
            Cm[rr][cc] = s;                                                  \
        }                                                                    \
        __syncthreads();                                                     \
    } while (0)

__global__ __launch_bounds__(256)
void solve_kernel(const float* __restrict__ lridge, const float* __restrict__ lgamma)
{
    __shared__ float sG[32][33], sM[32][33], sL[32][33], sLi[32][33];
    __shared__ float sAw[32][33], sT[32][33];
    __shared__ float sCv[64][33], sBv[64][33];
    __shared__ float sScale;

    int bh = blockIdx.x;
    int tid = threadIdx.x;

    const float* base = g_part + (size_t)bh * NCH * 4096;
    for (int idx = tid; idx < 4096; idx += 256) {
        float s = 0.f;
        #pragma unroll
        for (int c = 0; c < NCH; c++) s += base[(size_t)c * 4096 + idx];
        if (idx < 1024)      sG[idx >> 5][idx & 31] = s;
        else if (idx < 2048) sM[(idx - 1024) >> 5][idx & 31] = s;
        else { int e = idx - 2048; sCv[e >> 5][e & 31] = s; }
    }
    __syncthreads();
    if (tid < 32) sG[tid][tid] += expf(lridge[0]);
    __syncthreads();

    if (tid < 32) {
        int i = tid;
        for (int j = 0; j < 32; j++) {
            if (i == j) {
                float s = sG[j][j];
                for (int k = 0; k < j; k++) s -= sL[j][k] * sL[j][k];
                sL[j][j] = sqrtf(fmaxf(s, 1e-30f));
            }
            __syncwarp();
            if (i > j) {
                float s = sG[i][j];
                for (int k = 0; k < j; k++) s -= sL[i][k] * sL[j][k];
                sL[i][j] = s / sL[j][j];
            } else if (i < j) {
                sL[i][j] = 0.f;
            }
            __syncwarp();
        }
        int j = tid;
        for (int i2 = 0; i2 < 32; i2++) sLi[i2][j] = 0.f;
        for (int i2 = j; i2 < 32; i2++) {
            float s = (i2 == j) ? 1.f : 0.f;
            for (int k = j; k < i2; k++) s -= sL[i2][k] * sLi[k][j];
            sLi[i2][j] = s / sL[i2][i2];
        }
    }
    __syncthreads();

    MM32(sT, sLi, sM);
    for (int e = tid; e < 1024; e += 256) {
        int rr = e >> 5, cc = e & 31; float s = 0.f;
        #pragma unroll
        for (int k2 = 0; k2 < 32; k2++) s += sT[rr][k2] * sLi[cc][k2];
        sAw[rr][cc] = s;
    }
    __syncthreads();

    if (tid < 32) {
        int i = tid;
        float v = 1.0f + 0.37f * (float)i;
        float sig = 0.f;
        for (int it = 0; it < 64; it++) {
            float u = 0.f;
            #pragma unroll
            for (int k = 0; k < 32; k++) u += sAw[i][k] * __shfl_sync(0xffffffffu, v, k);
            float w = 0.f;
            #pragma unroll
            for (int k = 0; k < 32; k++) w += sAw[k][i] * __shfl_sync(0xffffffffu, u, k);
            float n2 = w * w;
            #pragma unroll
            for (int o = 16; o > 0; o >>= 1) n2 += __shfl_xor_sync(0xffffffffu, n2, o);
            float nrm = sqrtf(n2);
            v = w / fmaxf(nrm, 1e-30f);
            sig = sqrtf(nrm);
        }
        if (i == 0) {
            float gamma = expf(lgamma[0]);
            float gc = fminf(gamma, 1.0f);
            float s0 = fmaxf(sig, 1e-8f);
            sScale = gc / fmaxf(s0, 1.0f);
        }
    }
    __syncthreads();
    float scl = sScale;
    for (int e = tid; e < 1024; e += 256) sAw[e >> 5][e & 31] *= scl;
    __syncthreads();

    MM32(sT, sAw, sAw);
    MM32(sM, sT, sT);
    MM32(sG, sM, sLi);
    MM32(sT, sL, sG);

    for (int e = tid; e < 2048; e += 256) {
        int dd = e >> 5, rr = e & 31; float s = 0.f;
        #pragma unroll
        for (int k2 = 0; k2 < 32; k2++) s += sCv[dd][k2] * sLi[rr][k2];
        sBv[dd][rr] = s;
    }
    __syncthreads();
    for (int e = tid; e < 2048; e += 256) {
        int dd = e >> 5, rr = e & 31; float s = 0.f;
        #pragma unroll
        for (int k2 = 0; k2 < 32; k2++) s += sBv[dd][k2] * sLi[k2][rr];
        sCv[dd][rr] = s;
    }
    __syncthreads();

    float* tm = g_Tmat + (size_t)bh * DH_ * R_;
    for (int e = tid; e < 2048; e += 256) {
        int dd = e >> 5, rr = e & 31; float s = 0.f;
        #pragma unroll
        for (int k2 = 0; k2 < 32; k2++) s += sCv[dd][k2] * sT[k2][rr];
        tm[dd * R_ + rr] = s;
    }
}

// ---------------- W2_b[n][h*32+r] = sum_d Tmat_bh[d][r] * Wo[h*64+d][n] ----------------
__global__ __launch_bounds__(256)
void w2_kernel()
{
    int bh = blockIdx.x;            // b*16+h
    int h  = bh & 15;
    int b  = bh >> 4;
    int n  = blockIdx.y * 256 + threadIdx.x;   // output column 0..1023

    __shared__ float Tm[DH_][R_ + 1];
    for (int i = threadIdx.x; i < DH_ * R_; i += 256)
        Tm[i >> 5][i & 31] = g_Tmat[(size_t)bh * DH_ * R_ + i];
    __syncthreads();

    const __nv_bfloat16* wh = g_Woth + (size_t)n * D_ + h * DH_;
    const __nv_bfloat16* wl = g_Wotl + (size_t)n * D_ + h * DH_;

    float s[R_];
    #pragma unroll
    for (int r = 0; r < R_; r++) s[r] = 0.f;
    for (int d = 0; d < DH_; d++) {
        float w = __bfloat162float(wh[d]) + __bfloat162float(wl[d]);
        #pragma unroll
        for (int r = 0; r < R_; r++) s[r] += Tm[d][r] * w;
    }
    size_t base = ((size_t)b * 1024 + n) * ZK + h * R_;
    #pragma unroll
    for (int r = 0; r < R_; r++) {
        __nv_bfloat16 hv = __float2bfloat16(s[r]);
        g_W2h[base + r] = hv;
        g_W2l[base + r] = __float2bfloat16(s[r] - __bfloat162float(hv));
    }
}

// ---------------- launcher ----------------
extern "C" void kernel_launch(void* const* d_in, const int* in_sizes, int n_in,
                              void* d_out, int out_size)
{
    const float* hs     = (const float*)d_in[0];
    const float* Wk     = (const float*)d_in[1];
    const float* Wq     = (const float*)d_in[2];
    const float* Wv     = (const float*)d_in[3];
    const float* Wo     = (const float*)d_in[4];
    const float* lns    = (const float*)d_in[5];
    const float* lnb    = (const float*)d_in[6];
    const float* gate   = (const float*)d_in[7];
    const float* lridge = (const float*)d_in[8];
    const float* lgamma = (const float*)d_in[9];
    const int*   pl     = (const int*)d_in[10];
    float* out = (float*)d_out;

    cudaFuncSetAttribute(mma_gemm_kernel<0>,
                         cudaFuncAttributeMaxDynamicSharedMemorySize, GEMM_SMEM);
    cudaFuncSetAttribute(mma_gemm_kernel<1>,
                         cudaFuncAttributeMaxDynamicSharedMemorySize, GEMM_SMEM);

    ln_split_kernel<<<MROWS, 256>>>(hs, lns, lnb);

    trans_split_kernel<<<dim3(32, 32, 4), 256>>>(Wk, Wq, Wv, Wo);

    mma_gemm_kernel<0><<<dim3(2048 / BN, MROWS / BM), 256, GEMM_SMEM>>>(nullptr, nullptr, pl);

    build_partial_kernel<<<dim3(BH_, NCH), 256>>>(pl);
    solve_kernel<<<BH_, 256>>>(lridge, lgamma);
    w2_kernel<<<dim3(BH_, 4), 256>>>();

    mma_gemm_kernel<1><<<dim3(1024 / BN, MROWS / BM), 256, GEMM_SMEM>>>(out, gate, pl);
}